// round 11
// baseline (speedup 1.0000x reference)
#include <cuda_runtime.h>
#include <math.h>
#include <stdint.h>

#define BATCH 2
#define SEQ   2048
#define DIM   1024
#define NHEAD 16
#define HDIM  64
#define NTOK  (BATCH*SEQ)   // 4096

// ---------------------------------------------------------------------------
// Scratch
// ---------------------------------------------------------------------------
__device__ float g_zn  [NTOK*DIM];
__device__ float g_cn  [NTOK*DIM];
__device__ float g_hf  [NTOK*2*DIM];
__device__ float g_dzl [NTOK*DIM];
__device__ float g_gh  [NTOK*DIM];
__device__ float g_dz  [NTOK*DIM];
__device__ float g_QK  [NTOK*2*DIM];   // packed: cols [0,1024)=Q, [1024,2048)=K
__device__ float g_V   [NTOK*DIM];
__device__ float g_attn[NTOK*DIM];
__device__ float g_z1  [NTOK*DIM];
__device__ float g_hcu [NTOK*2*DIM];
__device__ float g_z1n [NTOK*DIM];
__device__ float g_h4  [NTOK*4*DIM];

// ---------------------------------------------------------------------------
// helpers
// ---------------------------------------------------------------------------
__device__ __forceinline__ uint32_t f2tf32(float f)
{
    uint32_t r;
    asm("cvt.rna.tf32.f32 %0, %1;" : "=r"(r) : "f"(f));
    return r;
}

__device__ __forceinline__ uint32_t bits2tf32(uint32_t b)
{
    return f2tf32(__uint_as_float(b));
}

__device__ __forceinline__ float tanh_fast(float x)
{
    float y;
    asm("tanh.approx.f32 %0, %1;" : "=f"(y) : "f"(x));
    return y;
}

__device__ __forceinline__ void mma_tf32(float* c, const uint32_t* a, const uint32_t* b)
{
    asm volatile("mma.sync.aligned.m16n8k8.row.col.f32.tf32.tf32.f32 "
                 "{%0,%1,%2,%3}, {%4,%5,%6,%7}, {%8,%9}, {%0,%1,%2,%3};"
                 : "+f"(c[0]), "+f"(c[1]), "+f"(c[2]), "+f"(c[3])
                 : "r"(a[0]), "r"(a[1]), "r"(a[2]), "r"(a[3]),
                   "r"(b[0]), "r"(b[1]));
}

// 4x (8x8 b16) ldmatrix == 4 tf32 fragments of an (8x4 b32) tile
__device__ __forceinline__ void ldsm_x4(uint32_t* r, uint32_t addr)
{
    asm volatile("ldmatrix.sync.aligned.m8n8.x4.shared.b16 {%0,%1,%2,%3}, [%4];"
                 : "=r"(r[0]), "=r"(r[1]), "=r"(r[2]), "=r"(r[3]) : "r"(addr));
}

__device__ __forceinline__ void cpasync16(uint32_t saddr, const void* g)
{
    asm volatile("cp.async.cg.shared.global [%0], [%1], 16;\n" :: "r"(saddr), "l"(g));
}

// ---------------------------------------------------------------------------
// Fused RMSNorm pair + single RMSNorm
// ---------------------------------------------------------------------------
__global__ void rms2_kernel(const float* __restrict__ x0, const float* __restrict__ w0,
                            float* __restrict__ o0,
                            const float* __restrict__ x1, const float* __restrict__ w1,
                            float* __restrict__ o1)
{
    int rid = blockIdx.x;
    const float* x; const float* w; float* o; int row;
    if (rid < NTOK) { x = x0; w = w0; o = o0; row = rid; }
    else            { x = x1; w = w1; o = o1; row = rid - NTOK; }

    int t = threadIdx.x;
    const float4* xr = (const float4*)(x + (size_t)row * DIM);
    float4 v = xr[t];
    float ss = v.x*v.x + v.y*v.y + v.z*v.z + v.w*v.w;

    __shared__ float red[256];
    red[t] = ss;
    __syncthreads();
    for (int s = 128; s > 0; s >>= 1) {
        if (t < s) red[t] += red[t + s];
        __syncthreads();
    }
    float inv = rsqrtf(red[0] * (1.0f / DIM) + 1e-6f);
    float4 wv = ((const float4*)w)[t];
    float4 ov;
    ov.x = v.x * inv * wv.x;
    ov.y = v.y * inv * wv.y;
    ov.z = v.z * inv * wv.z;
    ov.w = v.w * inv * wv.w;
    ((float4*)(o + (size_t)row * DIM))[t] = ov;
}

__global__ void rms_kernel(const float* __restrict__ x, const float* __restrict__ w,
                           float* __restrict__ o)
{
    int row = blockIdx.x;
    int t   = threadIdx.x;
    const float4* xr = (const float4*)(x + (size_t)row * DIM);
    float4 v = xr[t];
    float ss = v.x*v.x + v.y*v.y + v.z*v.z + v.w*v.w;

    __shared__ float red[256];
    red[t] = ss;
    __syncthreads();
    for (int s = 128; s > 0; s >>= 1) {
        if (t < s) red[t] += red[t + s];
        __syncthreads();
    }
    float inv = rsqrtf(red[0] * (1.0f / DIM) + 1e-6f);
    float4 wv = ((const float4*)w)[t];
    float4 ov;
    ov.x = v.x * inv * wv.x;
    ov.y = v.y * inv * wv.y;
    ov.z = v.z * inv * wv.z;
    ov.w = v.w * inv * wv.w;
    ((float4*)(o + (size_t)row * DIM))[t] = ov;
}

// ---------------------------------------------------------------------------
// TF32 tensor-core GEMM:  C = EPI( ACT( gatherA @ W^T + bias ) )
// Block tile 128x128x32, 8 warps, warp tile 32x64.
// cp.async 3-stage pipeline (raw fp32 in smem); ldmatrix fragments with
// cvt.rna applied to fragment registers (same numerics as loader cvt).
// EPI: 0 none | 1 +res1 | 2 dt*(res1+v) | 3 v+res1+res2
// ACT: 0 none | 1 silu | 2 tanh
// ---------------------------------------------------------------------------
#define BM 128
#define BN 128
#define BK 32
#define KST 36
#define SA (BM * KST)                  // floats per matrix per stage
#define NSTAGE 3
#define GEMM_SMEM (NSTAGE * 2 * SA * 4)   // 110592 bytes

template<int ACT, int EPI, bool HAS_BIAS>
__global__ __launch_bounds__(256)
void gemm_tc_kernel(const float* __restrict__ p0, const float* __restrict__ p1,
                    const float* __restrict__ p2, const float* __restrict__ p3,
                    int s0, int s1, int s2, int s3,
                    const float* __restrict__ W0, const float* __restrict__ W1,
                    int wsplit,
                    const float* __restrict__ bias,
                    const float* __restrict__ res1, const float* __restrict__ res2,
                    const float* __restrict__ dtp,
                    float* __restrict__ C, int M, int N, int K)
{
    extern __shared__ float dsm[];   // [A0 W0][A1 W1][A2 W2]
    const uint32_t smem0 = (uint32_t)__cvta_generic_to_shared(dsm);

    const int bm = blockIdx.y * BM;
    const int bn = blockIdx.x * BN;
    const int tid  = threadIdx.x;
    const int warp = tid >> 5;
    const int lane = tid & 31;
    const int gid  = lane >> 2;
    const int tig  = lane & 3;
    const int wm   = warp >> 1;
    const int wn   = warp & 1;
    const int lg   = lane >> 3;
    const int lr   = lane & 7;

    const int rbase = tid >> 3;       // loader row 0..31 (+32 per it)
    const int c4    = (tid & 7) * 4;  // loader float col within BK

    const float* Wb = (bn < wsplit) ? (W0 + (size_t)bn * K)
                                    : (W1 + (size_t)(bn - wsplit) * K);

    float acc[2][8][4];
    #pragma unroll
    for (int mi = 0; mi < 2; mi++)
        #pragma unroll
        for (int ni = 0; ni < 8; ni++)
            #pragma unroll
            for (int r = 0; r < 4; r++) acc[mi][ni][r] = 0.0f;

    const int KT = K / BK;

    #define PREFETCH(KT_IDX, STAGE)                                                 \
    {                                                                               \
        const int gk  = (KT_IDX) * BK;                                              \
        const int seg = gk >> 10;                                                   \
        const float* sp = (seg == 0) ? p0 : (seg == 1) ? p1 : (seg == 2) ? p2 : p3; \
        const int    st = (seg == 0) ? s0 : (seg == 1) ? s1 : (seg == 2) ? s2 : s3; \
        const int    ko = (gk & 1023) + c4;                                         \
        const uint32_t base = smem0 + (uint32_t)((STAGE) * 2 * SA) * 4;             \
        _Pragma("unroll")                                                           \
        for (int it = 0; it < 4; it++) {                                            \
            int r = rbase + it * 32;                                                \
            cpasync16(base + (uint32_t)(r * KST + c4) * 4,                          \
                      sp + (size_t)(bm + r) * st + ko);                             \
            cpasync16(base + (uint32_t)(SA + r * KST + c4) * 4,                     \
                      Wb + (size_t)r * K + gk + c4);                                \
        }                                                                           \
        asm volatile("cp.async.commit_group;\n");                                   \
    }

    PREFETCH(0, 0);
    if (KT > 1) PREFETCH(1, 1);

    for (int kt = 0; kt < KT; kt++) {
        const int stage = kt % NSTAGE;
        if (kt + 2 < KT) {
            PREFETCH(kt + 2, (kt + 2) % NSTAGE);
            asm volatile("cp.async.wait_group 2;\n");
        } else if (kt + 1 < KT) {
            asm volatile("cp.async.wait_group 1;\n");
        } else {
            asm volatile("cp.async.wait_group 0;\n");
        }
        __syncthreads();

        const uint32_t sAaddr = smem0 + (uint32_t)(stage * 2 * SA) * 4;
        const uint32_t sWaddr = sAaddr + (uint32_t)SA * 4;

        #pragma unroll
        for (int k0 = 0; k0 < BK; k0 += 8) {
            uint32_t afr[2][4], bq[4][4];
            #pragma unroll
            for (int mi = 0; mi < 2; mi++) {
                int row = wm * 32 + mi * 16 + (lg & 1) * 8 + lr;
                int col = k0 + (lg >> 1) * 4;
                ldsm_x4(afr[mi], sAaddr + (uint32_t)(row * KST + col) * 4);
            }
            #pragma unroll
            for (int nip = 0; nip < 4; nip++) {
                int row = wn * 64 + (2 * nip + (lg >> 1)) * 8 + lr;
                int col = k0 + (lg & 1) * 4;
                ldsm_x4(bq[nip], sWaddr + (uint32_t)(row * KST + col) * 4);
            }
            #pragma unroll
            for (int mi = 0; mi < 2; mi++)
                #pragma unroll
                for (int j = 0; j < 4; j++)
                    afr[mi][j] = bits2tf32(afr[mi][j]);
            #pragma unroll
            for (int nip = 0; nip < 4; nip++)
                #pragma unroll
                for (int j = 0; j < 4; j++)
                    bq[nip][j] = bits2tf32(bq[nip][j]);
            #pragma unroll
            for (int mi = 0; mi < 2; mi++)
                #pragma unroll
                for (int ni = 0; ni < 8; ni++)
                    mma_tf32(acc[mi][ni], afr[mi], &bq[ni >> 1][(ni & 1) * 2]);
        }
        __syncthreads();
    }
    #undef PREFETCH

    const float dtv = (EPI == 2) ? dtp[0] : 0.0f;

    #pragma unroll
    for (int mi = 0; mi < 2; mi++) {
        int row = bm + wm * 32 + mi * 16 + gid;
        #pragma unroll
        for (int ni = 0; ni < 8; ni++) {
            int col = bn + wn * 64 + ni * 8 + 2 * tig;
            float b0 = 0.f, b1 = 0.f;
            if (HAS_BIAS) { b0 = bias[col]; b1 = bias[col + 1]; }
            #pragma unroll
            for (int half = 0; half < 2; half++) {
                int r = row + half * 8;
                float v0 = acc[mi][ni][half * 2 + 0] + b0;
                float v1 = acc[mi][ni][half * 2 + 1] + b1;
                if (ACT == 1) { v0 = v0 / (1.0f + __expf(-v0)); v1 = v1 / (1.0f + __expf(-v1)); }
                else if (ACT == 2) { v0 = tanhf(v0); v1 = tanhf(v1); }
                if (EPI == 1) {
                    const float2 rv = *(const float2*)(res1 + (size_t)r * N + col);
                    v0 += rv.x; v1 += rv.y;
                } else if (EPI == 2) {
                    const float2 rv = *(const float2*)(res1 + (size_t)r * N + col);
                    v0 = dtv * (rv.x + v0); v1 = dtv * (rv.y + v1);
                } else if (EPI == 3) {
                    const float2 ra2 = *(const float2*)(res1 + (size_t)r * N + col);
                    const float2 rb2 = *(const float2*)(res2 + (size_t)r * N + col);
                    v0 += ra2.x + rb2.x; v1 += ra2.y + rb2.y;
                }
                *(float2*)(C + (size_t)r * N + col) = make_float2(v0, v1);
            }
        }
    }
}

// ---------------------------------------------------------------------------
// Sigmoid attention (unchanged from R10)
// ---------------------------------------------------------------------------
#define AQ  128
#define AKV 32
#define KS2 68

__global__ __launch_bounds__(256)
void attn_tc_kernel(const float* __restrict__ Qp, const float* __restrict__ Kp,
                    int qstr,
                    const float* __restrict__ V, const float* __restrict__ temp,
                    float* __restrict__ O)
{
    __shared__ uint32_t Ks[AKV][KS2];
    __shared__ uint32_t Vs[AKV][72];
    __shared__ uint32_t Ps[AQ][KS2];

    const uint32_t ksBase = (uint32_t)__cvta_generic_to_shared(&Ks[0][0]);
    const uint32_t psBase = (uint32_t)__cvta_generic_to_shared(&Ps[0][0]);

    const int b = blockIdx.z, h = blockIdx.y;
    const int q0 = blockIdx.x * AQ;
    const int tid = threadIdx.x;
    const int warp = tid >> 5, lane = tid & 31;
    const int gid = lane >> 2, tig = lane & 3;
    const int lg  = lane >> 3, lr  = lane & 7;

    const float hs = 0.0625f * temp[0];   // 0.5 * (HD^-0.5 * temp)
    const size_t baseq  = ((size_t)(b * SEQ + q0)) * qstr + h * HDIM;
    const size_t basek  = ((size_t)(b * SEQ)) * qstr + h * HDIM;
    const size_t basev  = ((size_t)(b * SEQ)) * DIM + h * HDIM;
    const size_t baseo  = ((size_t)(b * SEQ + q0)) * DIM + h * HDIM;

    const int r0 = warp * 16 + gid;

    uint32_t qfr[8][4];
    {
        const float* Qr0 = Qp + baseq + (size_t)r0 * qstr;
        const float* Qr1 = Qr0 + (size_t)8 * qstr;
        #pragma unroll
        for (int kc = 0; kc < 8; kc++) {
            qfr[kc][0] = f2tf32(Qr0[kc * 8 + tig    ]);
            qfr[kc][1] = f2tf32(Qr1[kc * 8 + tig    ]);
            qfr[kc][2] = f2tf32(Qr0[kc * 8 + tig + 4]);
            qfr[kc][3] = f2tf32(Qr1[kc * 8 + tig + 4]);
        }
    }

    float acc_o[8][4];
    #pragma unroll
    for (int nb = 0; nb < 8; nb++)
        #pragma unroll
        for (int r = 0; r < 4; r++) acc_o[nb][r] = 0.0f;
    float rs0 = 0.0f, rs1 = 0.0f;

    for (int m0 = 0; m0 < SEQ; m0 += AKV) {
        __syncthreads();
        #pragma unroll
        for (int it = 0; it < 2; it++) {
            int f = tid + it * 256;
            int r = f >> 4, c4 = (f & 15) * 4;
            float4 kv = *(const float4*)(Kp + basek + (size_t)(m0 + r) * qstr + c4);
            Ks[r][c4] = f2tf32(kv.x); Ks[r][c4 + 1] = f2tf32(kv.y);
            Ks[r][c4 + 2] = f2tf32(kv.z); Ks[r][c4 + 3] = f2tf32(kv.w);
            float4 vv = *(const float4*)(V + basev + (size_t)(m0 + r) * DIM + c4);
            Vs[r][c4] = f2tf32(vv.x); Vs[r][c4 + 1] = f2tf32(vv.y);
            Vs[r][c4 + 2] = f2tf32(vv.z); Vs[r][c4 + 3] = f2tf32(vv.w);
        }
        __syncthreads();

        float acc_s[4][4] = {};
        #pragma unroll
        for (int k0 = 0; k0 < 64; k0 += 8) {
            uint32_t bK[2][4];
            #pragma unroll
            for (int nip = 0; nip < 2; nip++) {
                int row = (2 * nip + (lg >> 1)) * 8 + lr;
                int col = k0 + (lg & 1) * 4;
                ldsm_x4(bK[nip], ksBase + (uint32_t)(row * KS2 + col) * 4);
            }
            #pragma unroll
            for (int ni = 0; ni < 4; ni++)
                mma_tf32(acc_s[ni], qfr[k0 >> 3], &bK[ni >> 1][(ni & 1) * 2]);
        }

        #pragma unroll
        for (int nb = 0; nb < 4; nb++) {
            float s00 = fmaf(0.5f, tanh_fast(acc_s[nb][0] * hs), 0.5f);
            float s01 = fmaf(0.5f, tanh_fast(acc_s[nb][1] * hs), 0.5f);
            float s10 = fmaf(0.5f, tanh_fast(acc_s[nb][2] * hs), 0.5f);
            float s11 = fmaf(0.5f, tanh_fast(acc_s[nb][3] * hs), 0.5f);
            rs0 += s00 + s01;
            rs1 += s10 + s11;
            uint2 p0 = make_uint2(f2tf32(s00), f2tf32(s01));
            uint2 p1 = make_uint2(f2tf32(s10), f2tf32(s11));
            *(uint2*)&Ps[r0    ][nb * 8 + 2 * tig] = p0;
            *(uint2*)&Ps[r0 + 8][nb * 8 + 2 * tig] = p1;
        }
        __syncwarp();

        #pragma unroll
        for (int k0 = 0; k0 < 32; k0 += 8) {
            uint32_t aP[4];
            {
                int row = warp * 16 + (lg & 1) * 8 + lr;
                int col = k0 + (lg >> 1) * 4;
                ldsm_x4(aP, psBase + (uint32_t)(row * KS2 + col) * 4);
            }
            #pragma unroll
            for (int nb = 0; nb < 8; nb++) {
                uint32_t bfr[2];
                bfr[0] = Vs[k0 + tig    ][nb * 8 + gid];
                bfr[1] = Vs[k0 + tig + 4][nb * 8 + gid];
                mma_tf32(acc_o[nb], aP, bfr);
            }
        }
        __syncwarp();
    }

    rs0 += __shfl_xor_sync(0xffffffffu, rs0, 1);
    rs0 += __shfl_xor_sync(0xffffffffu, rs0, 2);
    rs1 += __shfl_xor_sync(0xffffffffu, rs1, 1);
    rs1 += __shfl_xor_sync(0xffffffffu, rs1, 2);
    const float inv0 = 1.0f / fmaxf(rs0, 1.0f);
    const float inv1 = 1.0f / fmaxf(rs1, 1.0f);

    float* O0 = O + baseo + (size_t)r0 * DIM;
    float* O1 = O0 + 8 * DIM;
    #pragma unroll
    for (int nb = 0; nb < 8; nb++) {
        int col = nb * 8 + 2 * tig;
        *(float2*)(O0 + col) = make_float2(acc_o[nb][0] * inv0, acc_o[nb][1] * inv0);
        *(float2*)(O1 + col) = make_float2(acc_o[nb][2] * inv1, acc_o[nb][3] * inv1);
    }
}

// ---------------------------------------------------------------------------
// Host-side dispatch
// ---------------------------------------------------------------------------
struct Seg { const float* p; int s; };

template<int ACT, int EPI, bool HAS_BIAS>
static void launch_gemm2(cudaStream_t st, const Seg* seg, int nseg,
                         const float* W0, const float* W1, int wsplit,
                         const float* bias,
                         const float* res1, const float* res2, const float* dtp,
                         float* C, int M, int N, int K)
{
    cudaFuncSetAttribute(gemm_tc_kernel<ACT, EPI, HAS_BIAS>,
                         cudaFuncAttributeMaxDynamicSharedMemorySize, GEMM_SMEM);
    const float* p0 = seg[0].p;                     int s0 = seg[0].s;
    const float* p1 = (nseg > 1) ? seg[1].p : p0;   int s1 = (nseg > 1) ? seg[1].s : s0;
    const float* p2 = (nseg > 2) ? seg[2].p : p0;   int s2 = (nseg > 2) ? seg[2].s : s0;
    const float* p3 = (nseg > 3) ? seg[3].p : p0;   int s3 = (nseg > 3) ? seg[3].s : s0;
    dim3 g(N / BN, M / BM), b(256);
    gemm_tc_kernel<ACT, EPI, HAS_BIAS><<<g, b, GEMM_SMEM, st>>>(
        p0, p1, p2, p3, s0, s1, s2, s3, W0, W1, wsplit,
        bias, res1, res2, dtp, C, M, N, K);
}

template<int ACT, int EPI, bool HAS_BIAS>
static void launch_gemm(cudaStream_t st, const Seg* seg, int nseg,
                        const float* W, const float* bias,
                        const float* res1, const float* res2, const float* dtp,
                        float* C, int M, int N, int K)
{
    launch_gemm2<ACT, EPI, HAS_BIAS>(st, seg, nseg, W, W, 1 << 30,
                                     bias, res1, res2, dtp, C, M, N, K);
}

static float* sym(const void* s)
{
    void* p = nullptr;
    cudaGetSymbolAddress(&p, s);
    return (float*)p;
}

extern "C" void kernel_launch(void* const* d_in, const int* in_sizes, int n_in,
                              void* d_out, int out_size)
{
    const float* z     = (const float*)d_in[0];
    const float* conn  = (const float*)d_in[1];
    const float* w_z   = (const float*)d_in[2];
    const float* w_c   = (const float*)d_in[3];
    const float* w_mlp = (const float*)d_in[4];
    const float* f_w1  = (const float*)d_in[5];
    const float* f_b1  = (const float*)d_in[6];
    const float* f_w2  = (const float*)d_in[7];
    const float* f_b2  = (const float*)d_in[8];
    const float* g_w1  = (const float*)d_in[9];
    const float* g_b1  = (const float*)d_in[10];
    const float* g_w2  = (const float*)d_in[11];
    const float* g_b2  = (const float*)d_in[12];
    const float* dt    = (const float*)d_in[13];
    const float* q_w   = (const float*)d_in[14];
    const float* k_w   = (const float*)d_in[15];
    const float* v_w   = (const float*)d_in[16];
    const float* o_w   = (const float*)d_in[17];
    const float* temp  = (const float*)d_in[18];
    const float* cu_w1 = (const float*)d_in[19];
    const float* cu_b1 = (const float*)d_in[20];
    const float* cu_w2 = (const float*)d_in[21];
    const float* cu_b2 = (const float*)d_in[22];
    const float* m_w1  = (const float*)d_in[23];
    const float* m_b1  = (const float*)d_in[24];
    const float* m_w2  = (const float*)d_in[25];
    const float* m_b2  = (const float*)d_in[26];

    float* out_z2 = (float*)d_out;
    float* out_cn = out_z2 + (size_t)NTOK * DIM;
    float* out_zb = out_cn + (size_t)NTOK * DIM;

    float* zn   = sym(g_zn);
    float* cn   = sym(g_cn);
    float* hf   = sym(g_hf);
    float* dzl  = sym(g_dzl);
    float* gh   = sym(g_gh);
    float* dz   = sym(g_dz);
    float* QKb  = sym(g_QK);
    float* Vb   = sym(g_V);
    float* attn = sym(g_attn);
    float* z1   = sym(g_z1);
    float* hcu  = sym(g_hcu);
    float* z1n  = sym(g_z1n);
    float* h4   = sym(g_h4);

    const int ND = NTOK * DIM;

    // Side stream + events (created once; every call performs identical work)
    static cudaStream_t s2 = nullptr;
    static cudaEvent_t evF1 = nullptr, evJ1 = nullptr, evF2 = nullptr, evJ2 = nullptr;
    if (!s2) {
        cudaStreamCreateWithFlags(&s2, cudaStreamNonBlocking);
        cudaEventCreateWithFlags(&evF1, cudaEventDisableTiming);
        cudaEventCreateWithFlags(&evJ1, cudaEventDisableTiming);
        cudaEventCreateWithFlags(&evF2, cudaEventDisableTiming);
        cudaEventCreateWithFlags(&evJ2, cudaEventDisableTiming);
    }
    cudaStream_t s0 = 0;   // default (captured) stream

    // 1. norms (fused pair) on main stream
    rms2_kernel<<<2 * NTOK, 256, 0, s0>>>(z, w_z, zn, conn, w_c, cn);

    // ---- fork 1: chain B (QK, V, attention) on s2; chain A (f/g) on s0 ----
    cudaEventRecord(evF1, s0);
    cudaStreamWaitEvent(s2, evF1, 0);

    // chain B (s2): z_before copy + projections + attention
    cudaMemcpyAsync(out_zb, z, (size_t)ND * sizeof(float),
                    cudaMemcpyDeviceToDevice, s2);
    { Seg s[2] = {{zn, DIM}, {cn, DIM}};
      launch_gemm2<0,0,false>(s2, s, 2, q_w, k_w, DIM, nullptr,
                              nullptr, nullptr, nullptr,
                              QKb, NTOK, 2*DIM, 2*DIM); }
    { Seg s[1] = {{zn, DIM}};
      launch_gemm<0,0,false>(s2, s, 1, v_w, nullptr, nullptr, nullptr, nullptr,
                             Vb, NTOK, DIM, DIM); }
    {
        dim3 g(SEQ / AQ, NHEAD, BATCH), b(256);
        attn_tc_kernel<<<g, b, 0, s2>>>(QKb, QKb + DIM, 2 * DIM, Vb, temp, attn);
    }
    cudaEventRecord(evJ1, s2);

    // chain A (s0): vector field + gamma
    { Seg s[1] = {{zn, DIM}};
      launch_gemm<1,0,true>(s0, s, 1, f_w1, f_b1, nullptr, nullptr, nullptr,
                            hf, NTOK, 2*DIM, DIM); }
    { Seg s[2] = {{hf, 2*DIM}, {hf + DIM, 2*DIM}};
      launch_gemm<0,0,true>(s0, s, 2, f_w2, f_b2, nullptr, nullptr, nullptr,
                            dzl, NTOK, DIM, 2*DIM); }
    { Seg s[2] = {{cn, DIM}, {dzl, DIM}};
      launch_gemm<2,0,true>(s0, s, 2, g_w1, g_b1, nullptr, nullptr, nullptr,
                            gh, NTOK, DIM, 2*DIM); }
    { Seg s[1] = {{gh, DIM}};
      launch_gemm<0,2,true>(s0, s, 1, g_w2, g_b2, dzl, nullptr, dt,
                            dz, NTOK, DIM, DIM); }

    // ---- join 1: o_w needs attn (B) and dz (A) ----
    cudaStreamWaitEvent(s0, evJ1, 0);

    // 6. z1 = z + dz + attn @ o_w^T
    { Seg s[1] = {{attn, DIM}};
      launch_gemm<0,3,false>(s0, s, 1, o_w, nullptr, z, dz, nullptr,
                             z1, NTOK, DIM, DIM); }

    // ---- fork 2: chain C (connection update) on s2; chain D (MLP) on s0 ----
    cudaEventRecord(evF2, s0);
    cudaStreamWaitEvent(s2, evF2, 0);

    // chain C (s2): conn_new
    { Seg s[3] = {{conn, DIM}, {z1, DIM}, {dz, DIM}};
      launch_gemm<1,0,true>(s2, s, 3, cu_w1, cu_b1, nullptr, nullptr, nullptr,
                            hcu, NTOK, 2*DIM, 3*DIM); }
    { Seg s[2] = {{hcu, 2*DIM}, {hcu + DIM, 2*DIM}};
      launch_gemm<0,1,true>(s2, s, 2, cu_w2, cu_b2, conn, nullptr, nullptr,
                            out_cn, NTOK, DIM, 2*DIM); }
    cudaEventRecord(evJ2, s2);

    // chain D (s0): MLP block
    rms_kernel<<<NTOK, 256, 0, s0>>>(z1, w_mlp, z1n);
    { Seg s[1] = {{z1n, DIM}};
      launch_gemm<1,0,true>(s0, s, 1, m_w1, m_b1, nullptr, nullptr, nullptr,
                            h4, NTOK, 4*DIM, DIM); }
    { Seg s[4] = {{h4, 4*DIM}, {h4 + DIM, 4*DIM}, {h4 + 2*DIM, 4*DIM}, {h4 + 3*DIM, 4*DIM}};
      launch_gemm<0,1,true>(s0, s, 4, m_w2, m_b2, z1, nullptr, nullptr,
                            out_z2, NTOK, DIM, 4*DIM); }

    // ---- join 2: everything back on the captured stream ----
    cudaStreamWaitEvent(s0, evJ2, 0);
}

// round 12
// speedup vs baseline: 1.0446x; 1.0446x over previous
#include <cuda_runtime.h>
#include <math.h>
#include <stdint.h>

#define BATCH 2
#define SEQ   2048
#define DIM   1024
#define NHEAD 16
#define HDIM  64
#define NTOK  (BATCH*SEQ)   // 4096

// ---------------------------------------------------------------------------
// Scratch
// ---------------------------------------------------------------------------
__device__ float g_zn  [NTOK*DIM];
__device__ float g_cn  [NTOK*DIM];
__device__ float g_hf  [NTOK*2*DIM];
__device__ float g_dzl [NTOK*DIM];
__device__ float g_gh  [NTOK*DIM];
__device__ float g_dz  [NTOK*DIM];
__device__ float g_QK  [NTOK*2*DIM];   // packed: cols [0,1024)=Q, [1024,2048)=K (tf32 bits)
__device__ float g_V   [NTOK*DIM];     // tf32 bits
__device__ float g_attn[NTOK*DIM];
__device__ float g_z1  [NTOK*DIM];
__device__ float g_hcu [NTOK*2*DIM];
__device__ float g_z1n [NTOK*DIM];
__device__ float g_h4  [NTOK*4*DIM];

// ---------------------------------------------------------------------------
// helpers
// ---------------------------------------------------------------------------
__device__ __forceinline__ uint32_t f2tf32(float f)
{
    uint32_t r;
    asm("cvt.rna.tf32.f32 %0, %1;" : "=r"(r) : "f"(f));
    return r;
}

__device__ __forceinline__ float tanh_fast(float x)
{
    float y;
    asm("tanh.approx.f32 %0, %1;" : "=f"(y) : "f"(x));
    return y;
}

__device__ __forceinline__ void mma_tf32(float* c, const uint32_t* a, const uint32_t* b)
{
    asm volatile("mma.sync.aligned.m16n8k8.row.col.f32.tf32.tf32.f32 "
                 "{%0,%1,%2,%3}, {%4,%5,%6,%7}, {%8,%9}, {%0,%1,%2,%3};"
                 : "+f"(c[0]), "+f"(c[1]), "+f"(c[2]), "+f"(c[3])
                 : "r"(a[0]), "r"(a[1]), "r"(a[2]), "r"(a[3]),
                   "r"(b[0]), "r"(b[1]));
}

// 4x (8x8 b16) ldmatrix == 4 tf32 fragments of an (8x4 b32) tile
__device__ __forceinline__ void ldsm_x4(uint32_t* r, uint32_t addr)
{
    asm volatile("ldmatrix.sync.aligned.m8n8.x4.shared.b16 {%0,%1,%2,%3}, [%4];"
                 : "=r"(r[0]), "=r"(r[1]), "=r"(r[2]), "=r"(r[3]) : "r"(addr));
}

__device__ __forceinline__ void cpasync16(uint32_t saddr, const void* g)
{
    asm volatile("cp.async.cg.shared.global [%0], [%1], 16;\n" :: "r"(saddr), "l"(g));
}

// ---------------------------------------------------------------------------
// Fused RMSNorm pair + single RMSNorm
// ---------------------------------------------------------------------------
__global__ void rms2_kernel(const float* __restrict__ x0, const float* __restrict__ w0,
                            float* __restrict__ o0,
                            const float* __restrict__ x1, const float* __restrict__ w1,
                            float* __restrict__ o1)
{
    int rid = blockIdx.x;
    const float* x; const float* w; float* o; int row;
    if (rid < NTOK) { x = x0; w = w0; o = o0; row = rid; }
    else            { x = x1; w = w1; o = o1; row = rid - NTOK; }

    int t = threadIdx.x;
    const float4* xr = (const float4*)(x + (size_t)row * DIM);
    float4 v = xr[t];
    float ss = v.x*v.x + v.y*v.y + v.z*v.z + v.w*v.w;

    __shared__ float red[256];
    red[t] = ss;
    __syncthreads();
    for (int s = 128; s > 0; s >>= 1) {
        if (t < s) red[t] += red[t + s];
        __syncthreads();
    }
    float inv = rsqrtf(red[0] * (1.0f / DIM) + 1e-6f);
    float4 wv = ((const float4*)w)[t];
    float4 ov;
    ov.x = v.x * inv * wv.x;
    ov.y = v.y * inv * wv.y;
    ov.z = v.z * inv * wv.z;
    ov.w = v.w * inv * wv.w;
    ((float4*)(o + (size_t)row * DIM))[t] = ov;
}

__global__ void rms_kernel(const float* __restrict__ x, const float* __restrict__ w,
                           float* __restrict__ o)
{
    int row = blockIdx.x;
    int t   = threadIdx.x;
    const float4* xr = (const float4*)(x + (size_t)row * DIM);
    float4 v = xr[t];
    float ss = v.x*v.x + v.y*v.y + v.z*v.z + v.w*v.w;

    __shared__ float red[256];
    red[t] = ss;
    __syncthreads();
    for (int s = 128; s > 0; s >>= 1) {
        if (t < s) red[t] += red[t + s];
        __syncthreads();
    }
    float inv = rsqrtf(red[0] * (1.0f / DIM) + 1e-6f);
    float4 wv = ((const float4*)w)[t];
    float4 ov;
    ov.x = v.x * inv * wv.x;
    ov.y = v.y * inv * wv.y;
    ov.z = v.z * inv * wv.z;
    ov.w = v.w * inv * wv.w;
    ((float4*)(o + (size_t)row * DIM))[t] = ov;
}

// ---------------------------------------------------------------------------
// TF32 tensor-core GEMM (R10-proven version + TF32OUT store option):
//   C = EPI( ACT( gatherA @ W^T + bias ) )
// Block tile 128x128x32, 8 warps, warp tile 32x64.
// Loader: LDG -> cvt.rna.tf32 -> STS (register double-buffered, 2 smem stages).
// Inner loop: ldmatrix.x4 fragment loads.
// TF32OUT: store tf32-rna-rounded bits (for Q/K/V feeding attention).
// EPI: 0 none | 1 +res1 | 2 dt*(res1+v) | 3 v+res1+res2
// ACT: 0 none | 1 silu | 2 tanh
// ---------------------------------------------------------------------------
#define BM 128
#define BN 128
#define BK 32
#define KST 36
#define SA (BM * KST)
#define GEMM_SMEM (4 * SA * 4)

template<int ACT, int EPI, bool HAS_BIAS, bool TF32OUT>
__global__ __launch_bounds__(256)
void gemm_tc_kernel(const float* __restrict__ p0, const float* __restrict__ p1,
                    const float* __restrict__ p2, const float* __restrict__ p3,
                    int s0, int s1, int s2, int s3,
                    const float* __restrict__ W0, const float* __restrict__ W1,
                    int wsplit,
                    const float* __restrict__ bias,
                    const float* __restrict__ res1, const float* __restrict__ res2,
                    const float* __restrict__ dtp,
                    float* __restrict__ C, int M, int N, int K)
{
    extern __shared__ float dsm[];   // [A0][A1][W0][W1]
    const uint32_t smem0 = (uint32_t)__cvta_generic_to_shared(dsm);

    const int bm = blockIdx.y * BM;
    const int bn = blockIdx.x * BN;
    const int tid  = threadIdx.x;
    const int warp = tid >> 5;
    const int lane = tid & 31;
    const int gid  = lane >> 2;
    const int tig  = lane & 3;
    const int wm   = warp >> 1;
    const int wn   = warp & 1;
    const int lg   = lane >> 3;
    const int lr   = lane & 7;

    const int rbase = tid >> 3;
    const int c4    = (tid & 7) * 4;

    const float* Wb = (bn < wsplit) ? (W0 + (size_t)bn * K)
                                    : (W1 + (size_t)(bn - wsplit) * K);

    float acc[2][8][4];
    #pragma unroll
    for (int mi = 0; mi < 2; mi++)
        #pragma unroll
        for (int ni = 0; ni < 8; ni++)
            #pragma unroll
            for (int r = 0; r < 4; r++) acc[mi][ni][r] = 0.0f;

    const int KT = K / BK;

    float4 ra[4], rw[4];

    #define LDG_TILE(KT_IDX)                                                        \
    {                                                                               \
        const int gk  = (KT_IDX) * BK;                                              \
        const int seg = gk >> 10;                                                   \
        const float* sp = (seg == 0) ? p0 : (seg == 1) ? p1 : (seg == 2) ? p2 : p3; \
        const int    st = (seg == 0) ? s0 : (seg == 1) ? s1 : (seg == 2) ? s2 : s3; \
        const int    ko = (gk & 1023) + c4;                                         \
        _Pragma("unroll")                                                           \
        for (int it = 0; it < 4; it++)                                              \
            ra[it] = *(const float4*)(sp + (size_t)(bm + rbase + it * 32) * st + ko); \
        _Pragma("unroll")                                                           \
        for (int it = 0; it < 4; it++)                                              \
            rw[it] = *(const float4*)(Wb + (size_t)(rbase + it * 32) * K + gk + c4); \
    }

    #define STS_TILE(BUF)                                                           \
    {                                                                               \
        _Pragma("unroll")                                                           \
        for (int it = 0; it < 4; it++) {                                            \
            uint4 t4;                                                               \
            t4.x = f2tf32(ra[it].x); t4.y = f2tf32(ra[it].y);                       \
            t4.z = f2tf32(ra[it].z); t4.w = f2tf32(ra[it].w);                       \
            *(uint4*)(dsm + (BUF) * SA + (rbase + it * 32) * KST + c4) = t4;        \
            uint4 w4;                                                               \
            w4.x = f2tf32(rw[it].x); w4.y = f2tf32(rw[it].y);                       \
            w4.z = f2tf32(rw[it].z); w4.w = f2tf32(rw[it].w);                       \
            *(uint4*)(dsm + (2 + (BUF)) * SA + (rbase + it * 32) * KST + c4) = w4;  \
        }                                                                           \
    }

    LDG_TILE(0);
    STS_TILE(0);
    __syncthreads();

    int buf = 0;
    for (int kt = 0; kt < KT; kt++) {
        if (kt + 1 < KT) LDG_TILE(kt + 1);

        const uint32_t sAaddr = smem0 + (uint32_t)(buf * SA) * 4;
        const uint32_t sWaddr = smem0 + (uint32_t)((2 + buf) * SA) * 4;

        #pragma unroll
        for (int k0 = 0; k0 < BK; k0 += 8) {
            uint32_t afr[2][4], bq[4][4];
            #pragma unroll
            for (int mi = 0; mi < 2; mi++) {
                int row = wm * 32 + mi * 16 + (lg & 1) * 8 + lr;
                int col = k0 + (lg >> 1) * 4;
                ldsm_x4(afr[mi], sAaddr + (uint32_t)(row * KST + col) * 4);
            }
            #pragma unroll
            for (int nip = 0; nip < 4; nip++) {
                int row = wn * 64 + (2 * nip + (lg >> 1)) * 8 + lr;
                int col = k0 + (lg & 1) * 4;
                ldsm_x4(bq[nip], sWaddr + (uint32_t)(row * KST + col) * 4);
            }
            #pragma unroll
            for (int mi = 0; mi < 2; mi++)
                #pragma unroll
                for (int ni = 0; ni < 8; ni++)
                    mma_tf32(acc[mi][ni], afr[mi], &bq[ni >> 1][(ni & 1) * 2]);
        }

        if (kt + 1 < KT) STS_TILE(buf ^ 1);
        __syncthreads();
        buf ^= 1;
    }
    #undef LDG_TILE
    #undef STS_TILE

    const float dtv = (EPI == 2) ? dtp[0] : 0.0f;

    #pragma unroll
    for (int mi = 0; mi < 2; mi++) {
        int row = bm + wm * 32 + mi * 16 + gid;
        #pragma unroll
        for (int ni = 0; ni < 8; ni++) {
            int col = bn + wn * 64 + ni * 8 + 2 * tig;
            float b0 = 0.f, b1 = 0.f;
            if (HAS_BIAS) { b0 = bias[col]; b1 = bias[col + 1]; }
            #pragma unroll
            for (int half = 0; half < 2; half++) {
                int r = row + half * 8;
                float v0 = acc[mi][ni][half * 2 + 0] + b0;
                float v1 = acc[mi][ni][half * 2 + 1] + b1;
                if (ACT == 1) { v0 = v0 / (1.0f + __expf(-v0)); v1 = v1 / (1.0f + __expf(-v1)); }
                else if (ACT == 2) { v0 = tanhf(v0); v1 = tanhf(v1); }
                if (EPI == 1) {
                    const float2 rv = *(const float2*)(res1 + (size_t)r * N + col);
                    v0 += rv.x; v1 += rv.y;
                } else if (EPI == 2) {
                    const float2 rv = *(const float2*)(res1 + (size_t)r * N + col);
                    v0 = dtv * (rv.x + v0); v1 = dtv * (rv.y + v1);
                } else if (EPI == 3) {
                    const float2 ra2 = *(const float2*)(res1 + (size_t)r * N + col);
                    const float2 rb2 = *(const float2*)(res2 + (size_t)r * N + col);
                    v0 += ra2.x + rb2.x; v1 += ra2.y + rb2.y;
                }
                float o0 = v0, o1 = v1;
                if (TF32OUT) {
                    o0 = __uint_as_float(f2tf32(v0));
                    o1 = __uint_as_float(f2tf32(v1));
                }
                *(float2*)(C + (size_t)r * N + col) = make_float2(o0, o1);
            }
        }
    }
}

// ---------------------------------------------------------------------------
// Sigmoid attention: cp.async 3-stage KV pipeline, zero inner-loop cvt.
// Q/K/V arrive already tf32-rounded (producer GEMMs use TF32OUT).
// K/P fragments via ldmatrix; V scalar reads; P rounded after sigmoid.
// ---------------------------------------------------------------------------
#define AQ  128
#define AKV 32
#define KS2 68
#define VS2 72
#define NST 3
#define AKS_W (AKV * KS2)            // 2176 words per K stage
#define AVS_W (AKV * VS2)            // 2304 words per V stage
#define APS_W (AQ * KS2)             // 8704 words for P
#define ATTN_SMEM ((NST * (AKS_W + AVS_W) + APS_W) * 4)   // 88576 bytes

__global__ __launch_bounds__(256)
void attn_tc_kernel(const float* __restrict__ Qp, const float* __restrict__ Kp,
                    int qstr,
                    const float* __restrict__ V, const float* __restrict__ temp,
                    float* __restrict__ O)
{
    extern __shared__ uint32_t aw[];
    const uint32_t sBase  = (uint32_t)__cvta_generic_to_shared(aw);
    const int vsW = NST * AKS_W;                 // word offset of V stages
    const int psW = NST * (AKS_W + AVS_W);       // word offset of Ps
    const uint32_t psAddr = sBase + (uint32_t)psW * 4;

    const int b = blockIdx.z, h = blockIdx.y;
    const int q0 = blockIdx.x * AQ;
    const int tid = threadIdx.x;
    const int warp = tid >> 5, lane = tid & 31;
    const int gid = lane >> 2, tig = lane & 3;
    const int lg  = lane >> 3, lr  = lane & 7;

    const float hs = 0.0625f * temp[0];   // 0.5 * (HD^-0.5 * temp)
    const size_t baseq  = ((size_t)(b * SEQ + q0)) * qstr + h * HDIM;
    const size_t basek  = ((size_t)(b * SEQ)) * qstr + h * HDIM;
    const size_t basev  = ((size_t)(b * SEQ)) * DIM + h * HDIM;
    const size_t baseo  = ((size_t)(b * SEQ + q0)) * DIM + h * HDIM;

    const int r0 = warp * 16 + gid;

    // Q fragments: raw bit loads (already tf32-rounded by projection GEMM)
    uint32_t qfr[8][4];
    {
        const float* Qr0 = Qp + baseq + (size_t)r0 * qstr;
        const float* Qr1 = Qr0 + (size_t)8 * qstr;
        #pragma unroll
        for (int kc = 0; kc < 8; kc++) {
            qfr[kc][0] = __float_as_uint(Qr0[kc * 8 + tig    ]);
            qfr[kc][1] = __float_as_uint(Qr1[kc * 8 + tig    ]);
            qfr[kc][2] = __float_as_uint(Qr0[kc * 8 + tig + 4]);
            qfr[kc][3] = __float_as_uint(Qr1[kc * 8 + tig + 4]);
        }
    }

    // loader mapping: 512 float4 per K tile + 512 per V tile; 2 each per thread
    const int lrow0 = tid >> 4;                  // 0..15, +16 on second it
    const int lc4   = (tid & 15) * 4;

    #define APREFETCH(TILE, STAGE)                                                  \
    {                                                                               \
        const int m0p = (TILE) * AKV;                                               \
        const uint32_t kBase = sBase + (uint32_t)((STAGE) * AKS_W) * 4;             \
        const uint32_t vBase = sBase + (uint32_t)(vsW + (STAGE) * AVS_W) * 4;       \
        _Pragma("unroll")                                                           \
        for (int it = 0; it < 2; it++) {                                            \
            int r = lrow0 + it * 16;                                                \
            cpasync16(kBase + (uint32_t)(r * KS2 + lc4) * 4,                        \
                      Kp + basek + (size_t)(m0p + r) * qstr + lc4);                 \
            cpasync16(vBase + (uint32_t)(r * VS2 + lc4) * 4,                        \
                      V + basev + (size_t)(m0p + r) * DIM + lc4);                   \
        }                                                                           \
        asm volatile("cp.async.commit_group;\n");                                   \
    }

    float acc_o[8][4];
    #pragma unroll
    for (int nb = 0; nb < 8; nb++)
        #pragma unroll
        for (int r = 0; r < 4; r++) acc_o[nb][r] = 0.0f;
    float rs0 = 0.0f, rs1 = 0.0f;

    const int NT = SEQ / AKV;                    // 64
    APREFETCH(0, 0);
    APREFETCH(1, 1);

    for (int m = 0; m < NT; m++) {
        const int stage = m % NST;
        if (m + 1 < NT) {
            asm volatile("cp.async.wait_group 1;\n");
        } else {
            asm volatile("cp.async.wait_group 0;\n");
        }
        __syncthreads();
        // prefetch after the barrier: stage (m+2)%3 was last read at iter m-1,
        // and every warp has passed the barrier => safe to overwrite.
        if (m + 2 < NT) APREFETCH(m + 2, (m + 2) % NST);

        const uint32_t ksAddr = sBase + (uint32_t)(stage * AKS_W) * 4;
        const uint32_t vsOffW = vsW + stage * AVS_W;

        // S = Q @ K^T  (warp: 16 x 32), K fragments via ldmatrix (no cvt)
        float acc_s[4][4] = {};
        #pragma unroll
        for (int k0 = 0; k0 < 64; k0 += 8) {
            uint32_t bK[2][4];
            #pragma unroll
            for (int nip = 0; nip < 2; nip++) {
                int row = (2 * nip + (lg >> 1)) * 8 + lr;
                int col = k0 + (lg & 1) * 4;
                ldsm_x4(bK[nip], ksAddr + (uint32_t)(row * KS2 + col) * 4);
            }
            #pragma unroll
            for (int ni = 0; ni < 4; ni++)
                mma_tf32(acc_s[ni], qfr[k0 >> 3], &bK[ni >> 1][(ni & 1) * 2]);
        }

        // sigmoid = 0.5*tanh(s*scale/2) + 0.5 ; park tf32 bits in Ps
        #pragma unroll
        for (int nb = 0; nb < 4; nb++) {
            float s00 = fmaf(0.5f, tanh_fast(acc_s[nb][0] * hs), 0.5f);
            float s01 = fmaf(0.5f, tanh_fast(acc_s[nb][1] * hs), 0.5f);
            float s10 = fmaf(0.5f, tanh_fast(acc_s[nb][2] * hs), 0.5f);
            float s11 = fmaf(0.5f, tanh_fast(acc_s[nb][3] * hs), 0.5f);
            rs0 += s00 + s01;
            rs1 += s10 + s11;
            aw[psW + (r0    ) * KS2 + nb * 8 + 2 * tig    ] = f2tf32(s00);
            aw[psW + (r0    ) * KS2 + nb * 8 + 2 * tig + 1] = f2tf32(s01);
            aw[psW + (r0 + 8) * KS2 + nb * 8 + 2 * tig    ] = f2tf32(s10);
            aw[psW + (r0 + 8) * KS2 + nb * 8 + 2 * tig + 1] = f2tf32(s11);
        }
        __syncwarp();    // Ps rows are warp-private

        // O += P @ V : P fragments via ldmatrix, V scalar (already tf32)
        #pragma unroll
        for (int k0 = 0; k0 < 32; k0 += 8) {
            uint32_t aP[4];
            {
                int row = warp * 16 + (lg & 1) * 8 + lr;
                int col = k0 + (lg >> 1) * 4;
                ldsm_x4(aP, psAddr + (uint32_t)(row * KS2 + col) * 4);
            }
            #pragma unroll
            for (int nb = 0; nb < 8; nb++) {
                uint32_t bfr[2];
                bfr[0] = aw[vsOffW + (k0 + tig    ) * VS2 + nb * 8 + gid];
                bfr[1] = aw[vsOffW + (k0 + tig + 4) * VS2 + nb * 8 + gid];
                mma_tf32(acc_o[nb], aP, bfr);
            }
        }
        __syncwarp();    // Ps rewritten next iteration (warp-local)
    }
    #undef APREFETCH

    rs0 += __shfl_xor_sync(0xffffffffu, rs0, 1);
    rs0 += __shfl_xor_sync(0xffffffffu, rs0, 2);
    rs1 += __shfl_xor_sync(0xffffffffu, rs1, 1);
    rs1 += __shfl_xor_sync(0xffffffffu, rs1, 2);
    const float inv0 = 1.0f / fmaxf(rs0, 1.0f);
    const float inv1 = 1.0f / fmaxf(rs1, 1.0f);

    float* O0 = O + baseo + (size_t)r0 * DIM;
    float* O1 = O0 + 8 * DIM;
    #pragma unroll
    for (int nb = 0; nb < 8; nb++) {
        int col = nb * 8 + 2 * tig;
        *(float2*)(O0 + col) = make_float2(acc_o[nb][0] * inv0, acc_o[nb][1] * inv0);
        *(float2*)(O1 + col) = make_float2(acc_o[nb][2] * inv1, acc_o[nb][3] * inv1);
    }
}

// ---------------------------------------------------------------------------
// Host-side dispatch
// ---------------------------------------------------------------------------
struct Seg { const float* p; int s; };

template<int ACT, int EPI, bool HAS_BIAS, bool TF32OUT = false>
static void launch_gemm2(cudaStream_t st, const Seg* seg, int nseg,
                         const float* W0, const float* W1, int wsplit,
                         const float* bias,
                         const float* res1, const float* res2, const float* dtp,
                         float* C, int M, int N, int K)
{
    cudaFuncSetAttribute(gemm_tc_kernel<ACT, EPI, HAS_BIAS, TF32OUT>,
                         cudaFuncAttributeMaxDynamicSharedMemorySize, GEMM_SMEM);
    const float* p0 = seg[0].p;                     int s0 = seg[0].s;
    const float* p1 = (nseg > 1) ? seg[1].p : p0;   int s1 = (nseg > 1) ? seg[1].s : s0;
    const float* p2 = (nseg > 2) ? seg[2].p : p0;   int s2 = (nseg > 2) ? seg[2].s : s0;
    const float* p3 = (nseg > 3) ? seg[3].p : p0;   int s3 = (nseg > 3) ? seg[3].s : s0;
    dim3 g(N / BN, M / BM), b(256);
    gemm_tc_kernel<ACT, EPI, HAS_BIAS, TF32OUT><<<g, b, GEMM_SMEM, st>>>(
        p0, p1, p2, p3, s0, s1, s2, s3, W0, W1, wsplit,
        bias, res1, res2, dtp, C, M, N, K);
}

template<int ACT, int EPI, bool HAS_BIAS, bool TF32OUT = false>
static void launch_gemm(cudaStream_t st, const Seg* seg, int nseg,
                        const float* W, const float* bias,
                        const float* res1, const float* res2, const float* dtp,
                        float* C, int M, int N, int K)
{
    launch_gemm2<ACT, EPI, HAS_BIAS, TF32OUT>(st, seg, nseg, W, W, 1 << 30,
                                              bias, res1, res2, dtp, C, M, N, K);
}

static float* sym(const void* s)
{
    void* p = nullptr;
    cudaGetSymbolAddress(&p, s);
    return (float*)p;
}

extern "C" void kernel_launch(void* const* d_in, const int* in_sizes, int n_in,
                              void* d_out, int out_size)
{
    const float* z     = (const float*)d_in[0];
    const float* conn  = (const float*)d_in[1];
    const float* w_z   = (const float*)d_in[2];
    const float* w_c   = (const float*)d_in[3];
    const float* w_mlp = (const float*)d_in[4];
    const float* f_w1  = (const float*)d_in[5];
    const float* f_b1  = (const float*)d_in[6];
    const float* f_w2  = (const float*)d_in[7];
    const float* f_b2  = (const float*)d_in[8];
    const float* g_w1  = (const float*)d_in[9];
    const float* g_b1  = (const float*)d_in[10];
    const float* g_w2  = (const float*)d_in[11];
    const float* g_b2  = (const float*)d_in[12];
    const float* dt    = (const float*)d_in[13];
    const float* q_w   = (const float*)d_in[14];
    const float* k_w   = (const float*)d_in[15];
    const float* v_w   = (const float*)d_in[16];
    const float* o_w   = (const float*)d_in[17];
    const float* temp  = (const float*)d_in[18];
    const float* cu_w1 = (const float*)d_in[19];
    const float* cu_b1 = (const float*)d_in[20];
    const float* cu_w2 = (const float*)d_in[21];
    const float* cu_b2 = (const float*)d_in[22];
    const float* m_w1  = (const float*)d_in[23];
    const float* m_b1  = (const float*)d_in[24];
    const float* m_w2  = (const float*)d_in[25];
    const float* m_b2  = (const float*)d_in[26];

    float* out_z2 = (float*)d_out;
    float* out_cn = out_z2 + (size_t)NTOK * DIM;
    float* out_zb = out_cn + (size_t)NTOK * DIM;

    float* zn   = sym(g_zn);
    float* cn   = sym(g_cn);
    float* hf   = sym(g_hf);
    float* dzl  = sym(g_dzl);
    float* gh   = sym(g_gh);
    float* dz   = sym(g_dz);
    float* QKb  = sym(g_QK);
    float* Vb   = sym(g_V);
    float* attn = sym(g_attn);
    float* z1   = sym(g_z1);
    float* hcu  = sym(g_hcu);
    float* z1n  = sym(g_z1n);
    float* h4   = sym(g_h4);

    const int ND = NTOK * DIM;

    // Side stream + events (created once; every call performs identical work)
    static cudaStream_t s2 = nullptr;
    static cudaEvent_t evF1 = nullptr, evJ1 = nullptr, evF2 = nullptr, evJ2 = nullptr;
    if (!s2) {
        cudaStreamCreateWithFlags(&s2, cudaStreamNonBlocking);
        cudaEventCreateWithFlags(&evF1, cudaEventDisableTiming);
        cudaEventCreateWithFlags(&evJ1, cudaEventDisableTiming);
        cudaEventCreateWithFlags(&evF2, cudaEventDisableTiming);
        cudaEventCreateWithFlags(&evJ2, cudaEventDisableTiming);
    }
    cudaStream_t s0 = 0;   // default (captured) stream

    // 1. norms (fused pair) on main stream
    rms2_kernel<<<2 * NTOK, 256, 0, s0>>>(z, w_z, zn, conn, w_c, cn);

    // ---- fork 1: chain B (QK, V, attention) on s2; chain A (f/g) on s0 ----
    cudaEventRecord(evF1, s0);
    cudaStreamWaitEvent(s2, evF1, 0);

    // chain B (s2): z_before copy + projections (tf32-rounded stores) + attention
    cudaMemcpyAsync(out_zb, z, (size_t)ND * sizeof(float),
                    cudaMemcpyDeviceToDevice, s2);
    { Seg s[2] = {{zn, DIM}, {cn, DIM}};
      launch_gemm2<0,0,false,true>(s2, s, 2, q_w, k_w, DIM, nullptr,
                                   nullptr, nullptr, nullptr,
                                   QKb, NTOK, 2*DIM, 2*DIM); }
    { Seg s[1] = {{zn, DIM}};
      launch_gemm<0,0,false,true>(s2, s, 1, v_w, nullptr, nullptr, nullptr, nullptr,
                                  Vb, NTOK, DIM, DIM); }
    {
        cudaFuncSetAttribute(attn_tc_kernel,
                             cudaFuncAttributeMaxDynamicSharedMemorySize, ATTN_SMEM);
        dim3 g(SEQ / AQ, NHEAD, BATCH), b(256);
        attn_tc_kernel<<<g, b, ATTN_SMEM, s2>>>(QKb, QKb + DIM, 2 * DIM, Vb, temp, attn);
    }
    cudaEventRecord(evJ1, s2);

    // chain A (s0): vector field + gamma
    { Seg s[1] = {{zn, DIM}};
      launch_gemm<1,0,true>(s0, s, 1, f_w1, f_b1, nullptr, nullptr, nullptr,
                            hf, NTOK, 2*DIM, DIM); }
    { Seg s[2] = {{hf, 2*DIM}, {hf + DIM, 2*DIM}};
      launch_gemm<0,0,true>(s0, s, 2, f_w2, f_b2, nullptr, nullptr, nullptr,
                            dzl, NTOK, DIM, 2*DIM); }
    { Seg s[2] = {{cn, DIM}, {dzl, DIM}};
      launch_gemm<2,0,true>(s0, s, 2, g_w1, g_b1, nullptr, nullptr, nullptr,
                            gh, NTOK, DIM, 2*DIM); }
    { Seg s[1] = {{gh, DIM}};
      launch_gemm<0,2,true>(s0, s, 1, g_w2, g_b2, dzl, nullptr, dt,
                            dz, NTOK, DIM, DIM); }

    // ---- join 1: o_w needs attn (B) and dz (A) ----
    cudaStreamWaitEvent(s0, evJ1, 0);

    // 6. z1 = z + dz + attn @ o_w^T
    { Seg s[1] = {{attn, DIM}};
      launch_gemm<0,3,false>(s0, s, 1, o_w, nullptr, z, dz, nullptr,
                             z1, NTOK, DIM, DIM); }

    // ---- fork 2: chain C (connection update) on s2; chain D (MLP) on s0 ----
    cudaEventRecord(evF2, s0);
    cudaStreamWaitEvent(s2, evF2, 0);

    // chain C (s2): conn_new
    { Seg s[3] = {{conn, DIM}, {z1, DIM}, {dz, DIM}};
      launch_gemm<1,0,true>(s2, s, 3, cu_w1, cu_b1, nullptr, nullptr, nullptr,
                            hcu, NTOK, 2*DIM, 3*DIM); }
    { Seg s[2] = {{hcu, 2*DIM}, {hcu + DIM, 2*DIM}};
      launch_gemm<0,1,true>(s2, s, 2, cu_w2, cu_b2, conn, nullptr, nullptr,
                            out_cn, NTOK, DIM, 2*DIM); }
    cudaEventRecord(evJ2, s2);

    // chain D (s0): MLP block
    rms_kernel<<<NTOK, 256, 0, s0>>>(z1, w_mlp, z1n);
    { Seg s[1] = {{z1n, DIM}};
      launch_gemm<1,0,true>(s0, s, 1, m_w1, m_b1, nullptr, nullptr, nullptr,
                            h4, NTOK, 4*DIM, DIM); }
    { Seg s[4] = {{h4, 4*DIM}, {h4 + DIM, 4*DIM}, {h4 + 2*DIM, 4*DIM}, {h4 + 3*DIM, 4*DIM}};
      launch_gemm<0,1,true>(s0, s, 4, m_w2, m_b2, z1, nullptr, nullptr,
                            out_z2, NTOK, DIM, 4*DIM); }

    // ---- join 2: everything back on the captured stream ----
    cudaStreamWaitEvent(s0, evJ2, 0);
}

// round 13
// speedup vs baseline: 1.0798x; 1.0337x over previous
#include <cuda_runtime.h>
#include <math.h>
#include <stdint.h>

#define BATCH 2
#define SEQ   2048
#define DIM   1024
#define NHEAD 16
#define HDIM  64
#define NTOK  (BATCH*SEQ)   // 4096
#define MEG   (1024*1024)

// ---------------------------------------------------------------------------
// Scratch
// ---------------------------------------------------------------------------
__device__ float g_zn  [NTOK*DIM];     // tf32 bits
__device__ float g_cn  [NTOK*DIM];     // tf32 bits
__device__ float g_hf  [NTOK*2*DIM];   // tf32 bits
__device__ float g_dzl [NTOK*DIM];     // tf32 bits
__device__ float g_gh  [NTOK*DIM];     // tf32 bits
__device__ float g_dz  [NTOK*DIM];     // tf32 bits
__device__ float g_QK  [NTOK*2*DIM];   // tf32 bits; cols [0,1024)=Q, [1024,2048)=K
__device__ float g_V   [NTOK*DIM];     // tf32 bits
__device__ float g_attn[NTOK*DIM];     // tf32 bits
__device__ float g_z1  [NTOK*DIM];     // tf32 bits
__device__ float g_hcu [NTOK*2*DIM];   // tf32 bits
__device__ float g_z1n [NTOK*DIM];     // tf32 bits
__device__ float g_h4  [NTOK*4*DIM];   // tf32 bits
__device__ float g_connr[NTOK*DIM];    // rounded copy of conn
__device__ float g_wr  [29*MEG];       // rounded weights

// ---------------------------------------------------------------------------
// helpers
// ---------------------------------------------------------------------------
__device__ __forceinline__ uint32_t f2tf32(float f)
{
    uint32_t r;
    asm("cvt.rna.tf32.f32 %0, %1;" : "=r"(r) : "f"(f));
    return r;
}

__device__ __forceinline__ float tanh_fast(float x)
{
    float y;
    asm("tanh.approx.f32 %0, %1;" : "=f"(y) : "f"(x));
    return y;
}

__device__ __forceinline__ void mma_tf32(float* c, const uint32_t* a, const uint32_t* b)
{
    asm volatile("mma.sync.aligned.m16n8k8.row.col.f32.tf32.tf32.f32 "
                 "{%0,%1,%2,%3}, {%4,%5,%6,%7}, {%8,%9}, {%0,%1,%2,%3};"
                 : "+f"(c[0]), "+f"(c[1]), "+f"(c[2]), "+f"(c[3])
                 : "r"(a[0]), "r"(a[1]), "r"(a[2]), "r"(a[3]),
                   "r"(b[0]), "r"(b[1]));
}

// 4x (8x8 b16) ldmatrix == 4 tf32 fragments of an (8x4 b32) tile
__device__ __forceinline__ void ldsm_x4(uint32_t* r, uint32_t addr)
{
    asm volatile("ldmatrix.sync.aligned.m8n8.x4.shared.b16 {%0,%1,%2,%3}, [%4];"
                 : "=r"(r[0]), "=r"(r[1]), "=r"(r[2]), "=r"(r[3]) : "r"(addr));
}

__device__ __forceinline__ void cpasync16(uint32_t saddr, const void* g)
{
    asm volatile("cp.async.cg.shared.global [%0], [%1], 16;\n" :: "r"(saddr), "l"(g));
}

// ---------------------------------------------------------------------------
// roundcpy: dst = tf32_rna(src), vectorized
// ---------------------------------------------------------------------------
__global__ void roundcpy_kernel(const float* __restrict__ src, float* __restrict__ dst,
                                int n4)
{
    int i = blockIdx.x * blockDim.x + threadIdx.x;
    if (i < n4) {
        float4 v = ((const float4*)src)[i];
        uint4 t;
        t.x = f2tf32(v.x); t.y = f2tf32(v.y); t.z = f2tf32(v.z); t.w = f2tf32(v.w);
        ((uint4*)dst)[i] = t;
    }
}

// ---------------------------------------------------------------------------
// RMSNorm (outputs tf32-rounded — all consumers are GEMM A operands)
// ---------------------------------------------------------------------------
__global__ void rms2_kernel(const float* __restrict__ x0, const float* __restrict__ w0,
                            float* __restrict__ o0,
                            const float* __restrict__ x1, const float* __restrict__ w1,
                            float* __restrict__ o1)
{
    int rid = blockIdx.x;
    const float* x; const float* w; float* o; int row;
    if (rid < NTOK) { x = x0; w = w0; o = o0; row = rid; }
    else            { x = x1; w = w1; o = o1; row = rid - NTOK; }

    int t = threadIdx.x;
    const float4* xr = (const float4*)(x + (size_t)row * DIM);
    float4 v = xr[t];
    float ss = v.x*v.x + v.y*v.y + v.z*v.z + v.w*v.w;

    __shared__ float red[256];
    red[t] = ss;
    __syncthreads();
    for (int s = 128; s > 0; s >>= 1) {
        if (t < s) red[t] += red[t + s];
        __syncthreads();
    }
    float inv = rsqrtf(red[0] * (1.0f / DIM) + 1e-6f);
    float4 wv = ((const float4*)w)[t];
    uint4 ov;
    ov.x = f2tf32(v.x * inv * wv.x);
    ov.y = f2tf32(v.y * inv * wv.y);
    ov.z = f2tf32(v.z * inv * wv.z);
    ov.w = f2tf32(v.w * inv * wv.w);
    ((uint4*)(o + (size_t)row * DIM))[t] = ov;
}

__global__ void rms_kernel(const float* __restrict__ x, const float* __restrict__ w,
                           float* __restrict__ o)
{
    int row = blockIdx.x;
    int t   = threadIdx.x;
    const float4* xr = (const float4*)(x + (size_t)row * DIM);
    float4 v = xr[t];
    float ss = v.x*v.x + v.y*v.y + v.z*v.z + v.w*v.w;

    __shared__ float red[256];
    red[t] = ss;
    __syncthreads();
    for (int s = 128; s > 0; s >>= 1) {
        if (t < s) red[t] += red[t + s];
        __syncthreads();
    }
    float inv = rsqrtf(red[0] * (1.0f / DIM) + 1e-6f);
    float4 wv = ((const float4*)w)[t];
    uint4 ov;
    ov.x = f2tf32(v.x * inv * wv.x);
    ov.y = f2tf32(v.y * inv * wv.y);
    ov.z = f2tf32(v.z * inv * wv.z);
    ov.w = f2tf32(v.w * inv * wv.w);
    ((uint4*)(o + (size_t)row * DIM))[t] = ov;
}

// ---------------------------------------------------------------------------
// TF32 tensor-core GEMM, all inputs pre-rounded tf32 bits:
//   C = EPI( ACT( gatherA @ W^T + bias ) )
// Block tile 128x128x32, 8 warps, warp tile 32x64.
// 2-stage cp.async pipeline; inner loop pure ldsm+mma (zero cvt).
// TF32OUT: store tf32-rounded bits (for tensors feeding downstream GEMMs).
// EPI: 0 none | 1 +res1 | 2 dt*(res1+v) | 3 v+res1+res2
// ACT: 0 none | 1 silu | 2 tanh
// ---------------------------------------------------------------------------
#define BM 128
#define BN 128
#define BK 32
#define KST 36
#define SA (BM * KST)
#define GEMM_SMEM (4 * SA * 4)      // 2 stages x (A + W)

template<int ACT, int EPI, bool HAS_BIAS, bool TF32OUT>
__global__ __launch_bounds__(256)
void gemm_tc_kernel(const float* __restrict__ p0, const float* __restrict__ p1,
                    const float* __restrict__ p2, const float* __restrict__ p3,
                    int s0, int s1, int s2, int s3,
                    const float* __restrict__ W0, const float* __restrict__ W1,
                    int wsplit,
                    const float* __restrict__ bias,
                    const float* __restrict__ res1, const float* __restrict__ res2,
                    const float* __restrict__ dtp,
                    float* __restrict__ C, int M, int N, int K)
{
    extern __shared__ float dsm[];   // [A0][A1][W0][W1]
    const uint32_t smem0 = (uint32_t)__cvta_generic_to_shared(dsm);

    const int bm = blockIdx.y * BM;
    const int bn = blockIdx.x * BN;
    const int tid  = threadIdx.x;
    const int warp = tid >> 5;
    const int lane = tid & 31;
    const int gid  = lane >> 2;
    const int tig  = lane & 3;
    const int wm   = warp >> 1;
    const int wn   = warp & 1;
    const int lg   = lane >> 3;
    const int lr   = lane & 7;

    const int rbase = tid >> 3;       // loader row 0..31 (+32 per it)
    const int c4    = (tid & 7) * 4;  // loader float col within BK

    const float* Wb = (bn < wsplit) ? (W0 + (size_t)bn * K)
                                    : (W1 + (size_t)(bn - wsplit) * K);

    float acc[2][8][4];
    #pragma unroll
    for (int mi = 0; mi < 2; mi++)
        #pragma unroll
        for (int ni = 0; ni < 8; ni++)
            #pragma unroll
            for (int r = 0; r < 4; r++) acc[mi][ni][r] = 0.0f;

    const int KT = K / BK;

    #define PREFETCH(KT_IDX, BUF)                                                   \
    {                                                                               \
        const int gk  = (KT_IDX) * BK;                                              \
        const int seg = gk >> 10;                                                   \
        const float* sp = (seg == 0) ? p0 : (seg == 1) ? p1 : (seg == 2) ? p2 : p3; \
        const int    st = (seg == 0) ? s0 : (seg == 1) ? s1 : (seg == 2) ? s2 : s3; \
        const int    ko = (gk & 1023) + c4;                                         \
        _Pragma("unroll")                                                           \
        for (int it = 0; it < 4; it++) {                                            \
            int r = rbase + it * 32;                                                \
            cpasync16(smem0 + (uint32_t)((BUF) * SA + r * KST + c4) * 4,            \
                      sp + (size_t)(bm + r) * st + ko);                             \
            cpasync16(smem0 + (uint32_t)((2 + (BUF)) * SA + r * KST + c4) * 4,      \
                      Wb + (size_t)r * K + gk + c4);                                \
        }                                                                           \
        asm volatile("cp.async.commit_group;\n");                                   \
    }

    PREFETCH(0, 0);

    int buf = 0;
    for (int kt = 0; kt < KT; kt++) {
        if (kt + 1 < KT) {
            PREFETCH(kt + 1, buf ^ 1);
            asm volatile("cp.async.wait_group 1;\n");
        } else {
            asm volatile("cp.async.wait_group 0;\n");
        }
        __syncthreads();

        const uint32_t sAaddr = smem0 + (uint32_t)(buf * SA) * 4;
        const uint32_t sWaddr = smem0 + (uint32_t)((2 + buf) * SA) * 4;

        #pragma unroll
        for (int k0 = 0; k0 < BK; k0 += 8) {
            uint32_t afr[2][4], bq[4][4];
            #pragma unroll
            for (int mi = 0; mi < 2; mi++) {
                int row = wm * 32 + mi * 16 + (lg & 1) * 8 + lr;
                int col = k0 + (lg >> 1) * 4;
                ldsm_x4(afr[mi], sAaddr + (uint32_t)(row * KST + col) * 4);
            }
            #pragma unroll
            for (int nip = 0; nip < 4; nip++) {
                int row = wn * 64 + (2 * nip + (lg >> 1)) * 8 + lr;
                int col = k0 + (lg & 1) * 4;
                ldsm_x4(bq[nip], sWaddr + (uint32_t)(row * KST + col) * 4);
            }
            #pragma unroll
            for (int mi = 0; mi < 2; mi++)
                #pragma unroll
                for (int ni = 0; ni < 8; ni++)
                    mma_tf32(acc[mi][ni], afr[mi], &bq[ni >> 1][(ni & 1) * 2]);
        }
        __syncthreads();
        buf ^= 1;
    }
    #undef PREFETCH

    const float dtv = (EPI == 2) ? dtp[0] : 0.0f;

    #pragma unroll
    for (int mi = 0; mi < 2; mi++) {
        int row = bm + wm * 32 + mi * 16 + gid;
        #pragma unroll
        for (int ni = 0; ni < 8; ni++) {
            int col = bn + wn * 64 + ni * 8 + 2 * tig;
            float b0 = 0.f, b1 = 0.f;
            if (HAS_BIAS) { b0 = bias[col]; b1 = bias[col + 1]; }
            #pragma unroll
            for (int half = 0; half < 2; half++) {
                int r = row + half * 8;
                float v0 = acc[mi][ni][half * 2 + 0] + b0;
                float v1 = acc[mi][ni][half * 2 + 1] + b1;
                if (ACT == 1) { v0 = v0 / (1.0f + __expf(-v0)); v1 = v1 / (1.0f + __expf(-v1)); }
                else if (ACT == 2) { v0 = tanhf(v0); v1 = tanhf(v1); }
                if (EPI == 1) {
                    const float2 rv = *(const float2*)(res1 + (size_t)r * N + col);
                    v0 += rv.x; v1 += rv.y;
                } else if (EPI == 2) {
                    const float2 rv = *(const float2*)(res1 + (size_t)r * N + col);
                    v0 = dtv * (rv.x + v0); v1 = dtv * (rv.y + v1);
                } else if (EPI == 3) {
                    const float2 ra2 = *(const float2*)(res1 + (size_t)r * N + col);
                    const float2 rb2 = *(const float2*)(res2 + (size_t)r * N + col);
                    v0 += ra2.x + rb2.x; v1 += ra2.y + rb2.y;
                }
                float o0 = v0, o1 = v1;
                if (TF32OUT) {
                    o0 = __uint_as_float(f2tf32(v0));
                    o1 = __uint_as_float(f2tf32(v1));
                }
                *(float2*)(C + (size_t)r * N + col) = make_float2(o0, o1);
            }
        }
    }
}

// ---------------------------------------------------------------------------
// Sigmoid attention (R12 version; output now tf32-rounded for o_w GEMM)
// ---------------------------------------------------------------------------
#define AQ  128
#define AKV 32
#define KS2 68
#define VS2 72
#define NST 3
#define AKS_W (AKV * KS2)
#define AVS_W (AKV * VS2)
#define APS_W (AQ * KS2)
#define ATTN_SMEM ((NST * (AKS_W + AVS_W) + APS_W) * 4)

__global__ __launch_bounds__(256)
void attn_tc_kernel(const float* __restrict__ Qp, const float* __restrict__ Kp,
                    int qstr,
                    const float* __restrict__ V, const float* __restrict__ temp,
                    float* __restrict__ O)
{
    extern __shared__ uint32_t aw[];
    const uint32_t sBase  = (uint32_t)__cvta_generic_to_shared(aw);
    const int vsW = NST * AKS_W;
    const int psW = NST * (AKS_W + AVS_W);
    const uint32_t psAddr = sBase + (uint32_t)psW * 4;

    const int b = blockIdx.z, h = blockIdx.y;
    const int q0 = blockIdx.x * AQ;
    const int tid = threadIdx.x;
    const int warp = tid >> 5, lane = tid & 31;
    const int gid = lane >> 2, tig = lane & 3;
    const int lg  = lane >> 3, lr  = lane & 7;

    const float hs = 0.0625f * temp[0];
    const size_t baseq  = ((size_t)(b * SEQ + q0)) * qstr + h * HDIM;
    const size_t basek  = ((size_t)(b * SEQ)) * qstr + h * HDIM;
    const size_t basev  = ((size_t)(b * SEQ)) * DIM + h * HDIM;
    const size_t baseo  = ((size_t)(b * SEQ + q0)) * DIM + h * HDIM;

    const int r0 = warp * 16 + gid;

    uint32_t qfr[8][4];
    {
        const float* Qr0 = Qp + baseq + (size_t)r0 * qstr;
        const float* Qr1 = Qr0 + (size_t)8 * qstr;
        #pragma unroll
        for (int kc = 0; kc < 8; kc++) {
            qfr[kc][0] = __float_as_uint(Qr0[kc * 8 + tig    ]);
            qfr[kc][1] = __float_as_uint(Qr1[kc * 8 + tig    ]);
            qfr[kc][2] = __float_as_uint(Qr0[kc * 8 + tig + 4]);
            qfr[kc][3] = __float_as_uint(Qr1[kc * 8 + tig + 4]);
        }
    }

    const int lrow0 = tid >> 4;
    const int lc4   = (tid & 15) * 4;

    #define APREFETCH(TILE, STAGE)                                                  \
    {                                                                               \
        const int m0p = (TILE) * AKV;                                               \
        const uint32_t kBase = sBase + (uint32_t)((STAGE) * AKS_W) * 4;             \
        const uint32_t vBase = sBase + (uint32_t)(vsW + (STAGE) * AVS_W) * 4;       \
        _Pragma("unroll")                                                           \
        for (int it = 0; it < 2; it++) {                                            \
            int r = lrow0 + it * 16;                                                \
            cpasync16(kBase + (uint32_t)(r * KS2 + lc4) * 4,                        \
                      Kp + basek + (size_t)(m0p + r) * qstr + lc4);                 \
            cpasync16(vBase + (uint32_t)(r * VS2 + lc4) * 4,                        \
                      V + basev + (size_t)(m0p + r) * DIM + lc4);                   \
        }                                                                           \
        asm volatile("cp.async.commit_group;\n");                                   \
    }

    float acc_o[8][4];
    #pragma unroll
    for (int nb = 0; nb < 8; nb++)
        #pragma unroll
        for (int r = 0; r < 4; r++) acc_o[nb][r] = 0.0f;
    float rs0 = 0.0f, rs1 = 0.0f;

    const int NT = SEQ / AKV;
    APREFETCH(0, 0);
    APREFETCH(1, 1);

    for (int m = 0; m < NT; m++) {
        const int stage = m % NST;
        if (m + 1 < NT) {
            asm volatile("cp.async.wait_group 1;\n");
        } else {
            asm volatile("cp.async.wait_group 0;\n");
        }
        __syncthreads();
        if (m + 2 < NT) APREFETCH(m + 2, (m + 2) % NST);

        const uint32_t ksAddr = sBase + (uint32_t)(stage * AKS_W) * 4;
        const uint32_t vsOffW = vsW + stage * AVS_W;

        float acc_s[4][4] = {};
        #pragma unroll
        for (int k0 = 0; k0 < 64; k0 += 8) {
            uint32_t bK[2][4];
            #pragma unroll
            for (int nip = 0; nip < 2; nip++) {
                int row = (2 * nip + (lg >> 1)) * 8 + lr;
                int col = k0 + (lg & 1) * 4;
                ldsm_x4(bK[nip], ksAddr + (uint32_t)(row * KS2 + col) * 4);
            }
            #pragma unroll
            for (int ni = 0; ni < 4; ni++)
                mma_tf32(acc_s[ni], qfr[k0 >> 3], &bK[ni >> 1][(ni & 1) * 2]);
        }

        #pragma unroll
        for (int nb = 0; nb < 4; nb++) {
            float s00 = fmaf(0.5f, tanh_fast(acc_s[nb][0] * hs), 0.5f);
            float s01 = fmaf(0.5f, tanh_fast(acc_s[nb][1] * hs), 0.5f);
            float s10 = fmaf(0.5f, tanh_fast(acc_s[nb][2] * hs), 0.5f);
            float s11 = fmaf(0.5f, tanh_fast(acc_s[nb][3] * hs), 0.5f);
            rs0 += s00 + s01;
            rs1 += s10 + s11;
            aw[psW + (r0    ) * KS2 + nb * 8 + 2 * tig    ] = f2tf32(s00);
            aw[psW + (r0    ) * KS2 + nb * 8 + 2 * tig + 1] = f2tf32(s01);
            aw[psW + (r0 + 8) * KS2 + nb * 8 + 2 * tig    ] = f2tf32(s10);
            aw[psW + (r0 + 8) * KS2 + nb * 8 + 2 * tig + 1] = f2tf32(s11);
        }
        __syncwarp();

        #pragma unroll
        for (int k0 = 0; k0 < 32; k0 += 8) {
            uint32_t aP[4];
            {
                int row = warp * 16 + (lg & 1) * 8 + lr;
                int col = k0 + (lg >> 1) * 4;
                ldsm_x4(aP, psAddr + (uint32_t)(row * KS2 + col) * 4);
            }
            #pragma unroll
            for (int nb = 0; nb < 8; nb++) {
                uint32_t bfr[2];
                bfr[0] = aw[vsOffW + (k0 + tig    ) * VS2 + nb * 8 + gid];
                bfr[1] = aw[vsOffW + (k0 + tig + 4) * VS2 + nb * 8 + gid];
                mma_tf32(acc_o[nb], aP, bfr);
            }
        }
        __syncwarp();
    }
    #undef APREFETCH

    rs0 += __shfl_xor_sync(0xffffffffu, rs0, 1);
    rs0 += __shfl_xor_sync(0xffffffffu, rs0, 2);
    rs1 += __shfl_xor_sync(0xffffffffu, rs1, 1);
    rs1 += __shfl_xor_sync(0xffffffffu, rs1, 2);
    const float inv0 = 1.0f / fmaxf(rs0, 1.0f);
    const float inv1 = 1.0f / fmaxf(rs1, 1.0f);

    float* O0 = O + baseo + (size_t)r0 * DIM;
    float* O1 = O0 + 8 * DIM;
    #pragma unroll
    for (int nb = 0; nb < 8; nb++) {
        int col = nb * 8 + 2 * tig;
        // rounded store: attn feeds the o_w GEMM (A operand)
        uint2 a = make_uint2(f2tf32(acc_o[nb][0] * inv0), f2tf32(acc_o[nb][1] * inv0));
        uint2 c = make_uint2(f2tf32(acc_o[nb][2] * inv1), f2tf32(acc_o[nb][3] * inv1));
        *(uint2*)(O0 + col) = a;
        *(uint2*)(O1 + col) = c;
    }
}

// ---------------------------------------------------------------------------
// Host-side dispatch
// ---------------------------------------------------------------------------
struct Seg { const float* p; int s; };

template<int ACT, int EPI, bool HAS_BIAS, bool TF32OUT = false>
static void launch_gemm2(cudaStream_t st, const Seg* seg, int nseg,
                         const float* W0, const float* W1, int wsplit,
                         const float* bias,
                         const float* res1, const float* res2, const float* dtp,
                         float* C, int M, int N, int K)
{
    cudaFuncSetAttribute(gemm_tc_kernel<ACT, EPI, HAS_BIAS, TF32OUT>,
                         cudaFuncAttributeMaxDynamicSharedMemorySize, GEMM_SMEM);
    const float* p0 = seg[0].p;                     int s0 = seg[0].s;
    const float* p1 = (nseg > 1) ? seg[1].p : p0;   int s1 = (nseg > 1) ? seg[1].s : s0;
    const float* p2 = (nseg > 2) ? seg[2].p : p0;   int s2 = (nseg > 2) ? seg[2].s : s0;
    const float* p3 = (nseg > 3) ? seg[3].p : p0;   int s3 = (nseg > 3) ? seg[3].s : s0;
    dim3 g(N / BN, M / BM), b(256);
    gemm_tc_kernel<ACT, EPI, HAS_BIAS, TF32OUT><<<g, b, GEMM_SMEM, st>>>(
        p0, p1, p2, p3, s0, s1, s2, s3, W0, W1, wsplit,
        bias, res1, res2, dtp, C, M, N, K);
}

template<int ACT, int EPI, bool HAS_BIAS, bool TF32OUT = false>
static void launch_gemm(cudaStream_t st, const Seg* seg, int nseg,
                        const float* W, const float* bias,
                        const float* res1, const float* res2, const float* dtp,
                        float* C, int M, int N, int K)
{
    launch_gemm2<ACT, EPI, HAS_BIAS, TF32OUT>(st, seg, nseg, W, W, 1 << 30,
                                              bias, res1, res2, dtp, C, M, N, K);
}

static void roundcpy(cudaStream_t st, const float* src, float* dst, size_t n)
{
    int n4 = (int)(n / 4);
    roundcpy_kernel<<<(n4 + 255) / 256, 256, 0, st>>>(src, dst, n4);
}

static float* sym(const void* s)
{
    void* p = nullptr;
    cudaGetSymbolAddress(&p, s);
    return (float*)p;
}

extern "C" void kernel_launch(void* const* d_in, const int* in_sizes, int n_in,
                              void* d_out, int out_size)
{
    const float* z     = (const float*)d_in[0];
    const float* conn  = (const float*)d_in[1];
    const float* w_z   = (const float*)d_in[2];
    const float* w_c   = (const float*)d_in[3];
    const float* w_mlp = (const float*)d_in[4];
    const float* f_w1  = (const float*)d_in[5];
    const float* f_b1  = (const float*)d_in[6];
    const float* f_w2  = (const float*)d_in[7];
    const float* f_b2  = (const float*)d_in[8];
    const float* g_w1  = (const float*)d_in[9];
    const float* g_b1  = (const float*)d_in[10];
    const float* g_w2  = (const float*)d_in[11];
    const float* g_b2  = (const float*)d_in[12];
    const float* dt    = (const float*)d_in[13];
    const float* q_w   = (const float*)d_in[14];
    const float* k_w   = (const float*)d_in[15];
    const float* v_w   = (const float*)d_in[16];
    const float* o_w   = (const float*)d_in[17];
    const float* temp  = (const float*)d_in[18];
    const float* cu_w1 = (const float*)d_in[19];
    const float* cu_b1 = (const float*)d_in[20];
    const float* cu_w2 = (const float*)d_in[21];
    const float* cu_b2 = (const float*)d_in[22];
    const float* m_w1  = (const float*)d_in[23];
    const float* m_b1  = (const float*)d_in[24];
    const float* m_w2  = (const float*)d_in[25];
    const float* m_b2  = (const float*)d_in[26];

    float* out_z2 = (float*)d_out;
    float* out_cn = out_z2 + (size_t)NTOK * DIM;
    float* out_zb = out_cn + (size_t)NTOK * DIM;

    float* zn   = sym(g_zn);
    float* cn   = sym(g_cn);
    float* hf   = sym(g_hf);
    float* dzl  = sym(g_dzl);
    float* gh   = sym(g_gh);
    float* dz   = sym(g_dz);
    float* QKb  = sym(g_QK);
    float* Vb   = sym(g_V);
    float* attn = sym(g_attn);
    float* z1   = sym(g_z1);
    float* hcu  = sym(g_hcu);
    float* z1n  = sym(g_z1n);
    float* h4   = sym(g_h4);
    float* connr= sym(g_connr);
    float* wr   = sym(g_wr);

    // rounded-weight layout inside g_wr
    float* r_fw1 = wr;                    // 2M
    float* r_fw2 = r_fw1 + 2 * MEG;       // 2M
    float* r_gw1 = r_fw2 + 2 * MEG;       // 2M
    float* r_gw2 = r_gw1 + 2 * MEG;       // 1M
    float* r_qw  = r_gw2 + 1 * MEG;       // 2M
    float* r_kw  = r_qw  + 2 * MEG;       // 2M
    float* r_vw  = r_kw  + 2 * MEG;       // 1M
    float* r_ow  = r_vw  + 1 * MEG;       // 1M
    float* r_cw1 = r_ow  + 1 * MEG;       // 6M
    float* r_cw2 = r_cw1 + 6 * MEG;       // 2M
    float* r_mw1 = r_cw2 + 2 * MEG;       // 4M
    float* r_mw2 = r_mw1 + 4 * MEG;       // 4M

    const int ND = NTOK * DIM;

    static cudaStream_t s2 = nullptr;
    static cudaEvent_t evF1 = nullptr, evJ1 = nullptr, evF2 = nullptr, evJ2 = nullptr;
    if (!s2) {
        cudaStreamCreateWithFlags(&s2, cudaStreamNonBlocking);
        cudaEventCreateWithFlags(&evF1, cudaEventDisableTiming);
        cudaEventCreateWithFlags(&evJ1, cudaEventDisableTiming);
        cudaEventCreateWithFlags(&evF2, cudaEventDisableTiming);
        cudaEventCreateWithFlags(&evJ2, cudaEventDisableTiming);
    }
    cudaStream_t s0 = 0;

    // 1. norms (fused pair) on main stream
    rms2_kernel<<<2 * NTOK, 256, 0, s0>>>(z, w_z, zn, conn, w_c, cn);

    // ---- fork 1 ----
    cudaEventRecord(evF1, s0);
    cudaStreamWaitEvent(s2, evF1, 0);

    // chain B (s2): round q/k/v weights + conn copy, z_before, projections, attn
    cudaMemcpyAsync(out_zb, z, (size_t)ND * sizeof(float),
                    cudaMemcpyDeviceToDevice, s2);
    roundcpy(s2, q_w, r_qw, 2 * MEG);
    roundcpy(s2, k_w, r_kw, 2 * MEG);
    roundcpy(s2, v_w, r_vw, 1 * MEG);
    roundcpy(s2, conn, connr, (size_t)ND);
    { Seg s[2] = {{zn, DIM}, {cn, DIM}};
      launch_gemm2<0,0,false,true>(s2, s, 2, r_qw, r_kw, DIM, nullptr,
                                   nullptr, nullptr, nullptr,
                                   QKb, NTOK, 2*DIM, 2*DIM); }
    { Seg s[1] = {{zn, DIM}};
      launch_gemm<0,0,false,true>(s2, s, 1, r_vw, nullptr, nullptr, nullptr, nullptr,
                                  Vb, NTOK, DIM, DIM); }
    {
        cudaFuncSetAttribute(attn_tc_kernel,
                             cudaFuncAttributeMaxDynamicSharedMemorySize, ATTN_SMEM);
        dim3 g(SEQ / AQ, NHEAD, BATCH), b(256);
        attn_tc_kernel<<<g, b, ATTN_SMEM, s2>>>(QKb, QKb + DIM, 2 * DIM, Vb, temp, attn);
    }
    cudaEventRecord(evJ1, s2);

    // chain A (s0): round f/g/m weights, then vector field + gamma
    roundcpy(s0, f_w1, r_fw1, 2 * MEG);
    roundcpy(s0, f_w2, r_fw2, 2 * MEG);
    roundcpy(s0, g_w1, r_gw1, 2 * MEG);
    roundcpy(s0, g_w2, r_gw2, 1 * MEG);
    roundcpy(s0, m_w1, r_mw1, 4 * MEG);
    roundcpy(s0, m_w2, r_mw2, 4 * MEG);
    { Seg s[1] = {{zn, DIM}};
      launch_gemm<1,0,true,true>(s0, s, 1, r_fw1, f_b1, nullptr, nullptr, nullptr,
                                 hf, NTOK, 2*DIM, DIM); }
    { Seg s[2] = {{hf, 2*DIM}, {hf + DIM, 2*DIM}};
      launch_gemm<0,0,true,true>(s0, s, 2, r_fw2, f_b2, nullptr, nullptr, nullptr,
                                 dzl, NTOK, DIM, 2*DIM); }
    { Seg s[2] = {{cn, DIM}, {dzl, DIM}};
      launch_gemm<2,0,true,true>(s0, s, 2, r_gw1, g_b1, nullptr, nullptr, nullptr,
                                 gh, NTOK, DIM, 2*DIM); }
    { Seg s[1] = {{gh, DIM}};
      launch_gemm<0,2,true,true>(s0, s, 1, r_gw2, g_b2, dzl, nullptr, dt,
                                 dz, NTOK, DIM, DIM); }
    // rounds for weights used after join (fills s0 idle time waiting for attn)
    roundcpy(s0, o_w, r_ow, 1 * MEG);
    roundcpy(s0, cu_w1, r_cw1, 6 * MEG);
    roundcpy(s0, cu_w2, r_cw2, 2 * MEG);

    // ---- join 1 ----
    cudaStreamWaitEvent(s0, evJ1, 0);

    // 6. z1 = z + dz + attn @ o_w^T  (tf32-rounded: feeds cu_w1 / rms)
    { Seg s[1] = {{attn, DIM}};
      launch_gemm<0,3,false,true>(s0, s, 1, r_ow, nullptr, z, dz, nullptr,
                                  z1, NTOK, DIM, DIM); }

    // ---- fork 2 ----
    cudaEventRecord(evF2, s0);
    cudaStreamWaitEvent(s2, evF2, 0);

    // chain C (s2): conn_new
    { Seg s[3] = {{connr, DIM}, {z1, DIM}, {dz, DIM}};
      launch_gemm<1,0,true,true>(s2, s, 3, r_cw1, cu_b1, nullptr, nullptr, nullptr,
                                 hcu, NTOK, 2*DIM, 3*DIM); }
    { Seg s[2] = {{hcu, 2*DIM}, {hcu + DIM, 2*DIM}};
      launch_gemm<0,1,true,false>(s2, s, 2, r_cw2, cu_b2, conn, nullptr, nullptr,
                                  out_cn, NTOK, DIM, 2*DIM); }
    cudaEventRecord(evJ2, s2);

    // chain D (s0): MLP block
    rms_kernel<<<NTOK, 256, 0, s0>>>(z1, w_mlp, z1n);
    { Seg s[1] = {{z1n, DIM}};
      launch_gemm<1,0,true,true>(s0, s, 1, r_mw1, m_b1, nullptr, nullptr, nullptr,
                                 h4, NTOK, 4*DIM, DIM); }
    { Seg s[4] = {{h4, 4*DIM}, {h4 + DIM, 4*DIM}, {h4 + 2*DIM, 4*DIM}, {h4 + 3*DIM, 4*DIM}};
      launch_gemm<0,1,true,false>(s0, s, 4, r_mw2, m_b2, z1, nullptr, nullptr,
                                  out_z2, NTOK, DIM, 4*DIM); }

    // ---- join 2 ----
    cudaStreamWaitEvent(s0, evJ2, 0);
}

// round 14
// speedup vs baseline: 1.0889x; 1.0084x over previous
#include <cuda_runtime.h>
#include <math.h>
#include <stdint.h>

#define BATCH 2
#define SEQ   2048
#define DIM   1024
#define NHEAD 16
#define HDIM  64
#define NTOK  (BATCH*SEQ)   // 4096
#define MEG   (1024*1024)

// ---------------------------------------------------------------------------
// Scratch
// ---------------------------------------------------------------------------
__device__ float g_zn  [NTOK*DIM];     // tf32 bits
__device__ float g_cn  [NTOK*DIM];     // tf32 bits
__device__ float g_hf  [NTOK*2*DIM];   // tf32 bits
__device__ float g_dzl [NTOK*DIM];     // tf32 bits
__device__ float g_gh  [NTOK*DIM];     // tf32 bits
__device__ float g_dz  [NTOK*DIM];     // tf32 bits
__device__ float g_QK  [NTOK*2*DIM];   // tf32 bits; cols [0,1024)=Q, [1024,2048)=K
__device__ float g_V   [NTOK*DIM];     // tf32 bits
__device__ float g_attn[NTOK*DIM];     // tf32 bits
__device__ float g_z1  [NTOK*DIM];     // tf32 bits
__device__ float g_hcu [NTOK*2*DIM];   // tf32 bits
__device__ float g_z1n [NTOK*DIM];     // tf32 bits
__device__ float g_h4  [NTOK*4*DIM];   // tf32 bits
__device__ float g_connr[NTOK*DIM];    // rounded copy of conn
__device__ float g_wr  [29*MEG];       // rounded weights

// ---------------------------------------------------------------------------
// helpers
// ---------------------------------------------------------------------------
__device__ __forceinline__ uint32_t f2tf32(float f)
{
    uint32_t r;
    asm("cvt.rna.tf32.f32 %0, %1;" : "=r"(r) : "f"(f));
    return r;
}

__device__ __forceinline__ float tanh_fast(float x)
{
    float y;
    asm("tanh.approx.f32 %0, %1;" : "=f"(y) : "f"(x));
    return y;
}

__device__ __forceinline__ void mma_tf32(float* c, const uint32_t* a, const uint32_t* b)
{
    asm volatile("mma.sync.aligned.m16n8k8.row.col.f32.tf32.tf32.f32 "
                 "{%0,%1,%2,%3}, {%4,%5,%6,%7}, {%8,%9}, {%0,%1,%2,%3};"
                 : "+f"(c[0]), "+f"(c[1]), "+f"(c[2]), "+f"(c[3])
                 : "r"(a[0]), "r"(a[1]), "r"(a[2]), "r"(a[3]),
                   "r"(b[0]), "r"(b[1]));
}

// 4x (8x8 b16) ldmatrix == 4 tf32 fragments of an (8x4 b32) tile
__device__ __forceinline__ void ldsm_x4(uint32_t* r, uint32_t addr)
{
    asm volatile("ldmatrix.sync.aligned.m8n8.x4.shared.b16 {%0,%1,%2,%3}, [%4];"
                 : "=r"(r[0]), "=r"(r[1]), "=r"(r[2]), "=r"(r[3]) : "r"(addr));
}

__device__ __forceinline__ void cpasync16(uint32_t saddr, const void* g)
{
    asm volatile("cp.async.cg.shared.global [%0], [%1], 16;\n" :: "r"(saddr), "l"(g));
}

// ---------------------------------------------------------------------------
// roundcpy: dst = tf32_rna(src), vectorized
// ---------------------------------------------------------------------------
__global__ void roundcpy_kernel(const float* __restrict__ src, float* __restrict__ dst,
                                int n4)
{
    int i = blockIdx.x * blockDim.x + threadIdx.x;
    if (i < n4) {
        float4 v = ((const float4*)src)[i];
        uint4 t;
        t.x = f2tf32(v.x); t.y = f2tf32(v.y); t.z = f2tf32(v.z); t.w = f2tf32(v.w);
        ((uint4*)dst)[i] = t;
    }
}

// ---------------------------------------------------------------------------
// RMSNorm (outputs tf32-rounded — all consumers are GEMM A operands)
// ---------------------------------------------------------------------------
__global__ void rms2_kernel(const float* __restrict__ x0, const float* __restrict__ w0,
                            float* __restrict__ o0,
                            const float* __restrict__ x1, const float* __restrict__ w1,
                            float* __restrict__ o1)
{
    int rid = blockIdx.x;
    const float* x; const float* w; float* o; int row;
    if (rid < NTOK) { x = x0; w = w0; o = o0; row = rid; }
    else            { x = x1; w = w1; o = o1; row = rid - NTOK; }

    int t = threadIdx.x;
    const float4* xr = (const float4*)(x + (size_t)row * DIM);
    float4 v = xr[t];
    float ss = v.x*v.x + v.y*v.y + v.z*v.z + v.w*v.w;

    __shared__ float red[256];
    red[t] = ss;
    __syncthreads();
    for (int s = 128; s > 0; s >>= 1) {
        if (t < s) red[t] += red[t + s];
        __syncthreads();
    }
    float inv = rsqrtf(red[0] * (1.0f / DIM) + 1e-6f);
    float4 wv = ((const float4*)w)[t];
    uint4 ov;
    ov.x = f2tf32(v.x * inv * wv.x);
    ov.y = f2tf32(v.y * inv * wv.y);
    ov.z = f2tf32(v.z * inv * wv.z);
    ov.w = f2tf32(v.w * inv * wv.w);
    ((uint4*)(o + (size_t)row * DIM))[t] = ov;
}

__global__ void rms_kernel(const float* __restrict__ x, const float* __restrict__ w,
                           float* __restrict__ o)
{
    int row = blockIdx.x;
    int t   = threadIdx.x;
    const float4* xr = (const float4*)(x + (size_t)row * DIM);
    float4 v = xr[t];
    float ss = v.x*v.x + v.y*v.y + v.z*v.z + v.w*v.w;

    __shared__ float red[256];
    red[t] = ss;
    __syncthreads();
    for (int s = 128; s > 0; s >>= 1) {
        if (t < s) red[t] += red[t + s];
        __syncthreads();
    }
    float inv = rsqrtf(red[0] * (1.0f / DIM) + 1e-6f);
    float4 wv = ((const float4*)w)[t];
    uint4 ov;
    ov.x = f2tf32(v.x * inv * wv.x);
    ov.y = f2tf32(v.y * inv * wv.y);
    ov.z = f2tf32(v.z * inv * wv.z);
    ov.w = f2tf32(v.w * inv * wv.w);
    ((uint4*)(o + (size_t)row * DIM))[t] = ov;
}

// ---------------------------------------------------------------------------
// TF32 tensor-core GEMM, all inputs pre-rounded tf32 bits:
//   C = EPI( ACT( gatherA @ W^T + bias ) )
// Block tile 128x128x32, 8 warps, warp tile 32x64.
// 3-stage cp.async pipeline, ONE __syncthreads per k-iteration
// (prefetch after the barrier: overwritten stage was last read at kt-1).
// Inner loop pure ldsm+mma (zero cvt).
// TF32OUT: store tf32-rounded bits (for tensors feeding downstream GEMMs).
// EPI: 0 none | 1 +res1 | 2 dt*(res1+v) | 3 v+res1+res2
// ACT: 0 none | 1 silu | 2 tanh
// ---------------------------------------------------------------------------
#define BM 128
#define BN 128
#define BK 32
#define KST 36
#define SA (BM * KST)
#define GNST 3
#define GEMM_SMEM (GNST * 2 * SA * 4)   // 110592 bytes; 2 CTAs = 221 KB <= 228 KB

template<int ACT, int EPI, bool HAS_BIAS, bool TF32OUT>
__global__ __launch_bounds__(256)
void gemm_tc_kernel(const float* __restrict__ p0, const float* __restrict__ p1,
                    const float* __restrict__ p2, const float* __restrict__ p3,
                    int s0, int s1, int s2, int s3,
                    const float* __restrict__ W0, const float* __restrict__ W1,
                    int wsplit,
                    const float* __restrict__ bias,
                    const float* __restrict__ res1, const float* __restrict__ res2,
                    const float* __restrict__ dtp,
                    float* __restrict__ C, int M, int N, int K)
{
    extern __shared__ float dsm[];   // [A0 W0][A1 W1][A2 W2]
    const uint32_t smem0 = (uint32_t)__cvta_generic_to_shared(dsm);

    const int bm = blockIdx.y * BM;
    const int bn = blockIdx.x * BN;
    const int tid  = threadIdx.x;
    const int warp = tid >> 5;
    const int lane = tid & 31;
    const int gid  = lane >> 2;
    const int tig  = lane & 3;
    const int wm   = warp >> 1;
    const int wn   = warp & 1;
    const int lg   = lane >> 3;
    const int lr   = lane & 7;

    const int rbase = tid >> 3;       // loader row 0..31 (+32 per it)
    const int c4    = (tid & 7) * 4;  // loader float col within BK

    const float* Wb = (bn < wsplit) ? (W0 + (size_t)bn * K)
                                    : (W1 + (size_t)(bn - wsplit) * K);

    float acc[2][8][4];
    #pragma unroll
    for (int mi = 0; mi < 2; mi++)
        #pragma unroll
        for (int ni = 0; ni < 8; ni++)
            #pragma unroll
            for (int r = 0; r < 4; r++) acc[mi][ni][r] = 0.0f;

    const int KT = K / BK;

    #define PREFETCH(KT_IDX, STAGE)                                                 \
    {                                                                               \
        const int gk  = (KT_IDX) * BK;                                              \
        const int seg = gk >> 10;                                                   \
        const float* sp = (seg == 0) ? p0 : (seg == 1) ? p1 : (seg == 2) ? p2 : p3; \
        const int    st = (seg == 0) ? s0 : (seg == 1) ? s1 : (seg == 2) ? s2 : s3; \
        const int    ko = (gk & 1023) + c4;                                         \
        const uint32_t base = smem0 + (uint32_t)((STAGE) * 2 * SA) * 4;             \
        _Pragma("unroll")                                                           \
        for (int it = 0; it < 4; it++) {                                            \
            int r = rbase + it * 32;                                                \
            cpasync16(base + (uint32_t)(r * KST + c4) * 4,                          \
                      sp + (size_t)(bm + r) * st + ko);                             \
            cpasync16(base + (uint32_t)(SA + r * KST + c4) * 4,                     \
                      Wb + (size_t)r * K + gk + c4);                                \
        }                                                                           \
        asm volatile("cp.async.commit_group;\n");                                   \
    }

    PREFETCH(0, 0);
    PREFETCH(1, 1);

    for (int kt = 0; kt < KT; kt++) {
        const int stage = kt % GNST;
        if (kt + 1 < KT) {
            asm volatile("cp.async.wait_group 1;\n");
        } else {
            asm volatile("cp.async.wait_group 0;\n");
        }
        __syncthreads();
        // prefetch after the barrier: stage (kt+2)%3 was last read at iter kt-1,
        // and every warp passing this barrier finished that read.
        if (kt + 2 < KT) PREFETCH(kt + 2, (kt + 2) % GNST);

        const uint32_t sAaddr = smem0 + (uint32_t)(stage * 2 * SA) * 4;
        const uint32_t sWaddr = sAaddr + (uint32_t)SA * 4;

        #pragma unroll
        for (int k0 = 0; k0 < BK; k0 += 8) {
            uint32_t afr[2][4], bq[4][4];
            #pragma unroll
            for (int mi = 0; mi < 2; mi++) {
                int row = wm * 32 + mi * 16 + (lg & 1) * 8 + lr;
                int col = k0 + (lg >> 1) * 4;
                ldsm_x4(afr[mi], sAaddr + (uint32_t)(row * KST + col) * 4);
            }
            #pragma unroll
            for (int nip = 0; nip < 4; nip++) {
                int row = wn * 64 + (2 * nip + (lg >> 1)) * 8 + lr;
                int col = k0 + (lg & 1) * 4;
                ldsm_x4(bq[nip], sWaddr + (uint32_t)(row * KST + col) * 4);
            }
            #pragma unroll
            for (int mi = 0; mi < 2; mi++)
                #pragma unroll
                for (int ni = 0; ni < 8; ni++)
                    mma_tf32(acc[mi][ni], afr[mi], &bq[ni >> 1][(ni & 1) * 2]);
        }
        // no trailing sync: next overwrite of this stage is gated by the
        // barrier at iteration kt+1.
    }
    #undef PREFETCH

    const float dtv = (EPI == 2) ? dtp[0] : 0.0f;

    #pragma unroll
    for (int mi = 0; mi < 2; mi++) {
        int row = bm + wm * 32 + mi * 16 + gid;
        #pragma unroll
        for (int ni = 0; ni < 8; ni++) {
            int col = bn + wn * 64 + ni * 8 + 2 * tig;
            float b0 = 0.f, b1 = 0.f;
            if (HAS_BIAS) { b0 = bias[col]; b1 = bias[col + 1]; }
            #pragma unroll
            for (int half = 0; half < 2; half++) {
                int r = row + half * 8;
                float v0 = acc[mi][ni][half * 2 + 0] + b0;
                float v1 = acc[mi][ni][half * 2 + 1] + b1;
                if (ACT == 1) { v0 = v0 / (1.0f + __expf(-v0)); v1 = v1 / (1.0f + __expf(-v1)); }
                else if (ACT == 2) { v0 = tanhf(v0); v1 = tanhf(v1); }
                if (EPI == 1) {
                    const float2 rv = *(const float2*)(res1 + (size_t)r * N + col);
                    v0 += rv.x; v1 += rv.y;
                } else if (EPI == 2) {
                    const float2 rv = *(const float2*)(res1 + (size_t)r * N + col);
                    v0 = dtv * (rv.x + v0); v1 = dtv * (rv.y + v1);
                } else if (EPI == 3) {
                    const float2 ra2 = *(const float2*)(res1 + (size_t)r * N + col);
                    const float2 rb2 = *(const float2*)(res2 + (size_t)r * N + col);
                    v0 += ra2.x + rb2.x; v1 += ra2.y + rb2.y;
                }
                float o0 = v0, o1 = v1;
                if (TF32OUT) {
                    o0 = __uint_as_float(f2tf32(v0));
                    o1 = __uint_as_float(f2tf32(v1));
                }
                *(float2*)(C + (size_t)r * N + col) = make_float2(o0, o1);
            }
        }
    }
}

// ---------------------------------------------------------------------------
// Sigmoid attention (unchanged from R13)
// ---------------------------------------------------------------------------
#define AQ  128
#define AKV 32
#define KS2 68
#define VS2 72
#define NST 3
#define AKS_W (AKV * KS2)
#define AVS_W (AKV * VS2)
#define APS_W (AQ * KS2)
#define ATTN_SMEM ((NST * (AKS_W + AVS_W) + APS_W) * 4)

__global__ __launch_bounds__(256)
void attn_tc_kernel(const float* __restrict__ Qp, const float* __restrict__ Kp,
                    int qstr,
                    const float* __restrict__ V, const float* __restrict__ temp,
                    float* __restrict__ O)
{
    extern __shared__ uint32_t aw[];
    const uint32_t sBase  = (uint32_t)__cvta_generic_to_shared(aw);
    const int vsW = NST * AKS_W;
    const int psW = NST * (AKS_W + AVS_W);
    const uint32_t psAddr = sBase + (uint32_t)psW * 4;

    const int b = blockIdx.z, h = blockIdx.y;
    const int q0 = blockIdx.x * AQ;
    const int tid = threadIdx.x;
    const int warp = tid >> 5, lane = tid & 31;
    const int gid = lane >> 2, tig = lane & 3;
    const int lg  = lane >> 3, lr  = lane & 7;

    const float hs = 0.0625f * temp[0];
    const size_t baseq  = ((size_t)(b * SEQ + q0)) * qstr + h * HDIM;
    const size_t basek  = ((size_t)(b * SEQ)) * qstr + h * HDIM;
    const size_t basev  = ((size_t)(b * SEQ)) * DIM + h * HDIM;
    const size_t baseo  = ((size_t)(b * SEQ + q0)) * DIM + h * HDIM;

    const int r0 = warp * 16 + gid;

    uint32_t qfr[8][4];
    {
        const float* Qr0 = Qp + baseq + (size_t)r0 * qstr;
        const float* Qr1 = Qr0 + (size_t)8 * qstr;
        #pragma unroll
        for (int kc = 0; kc < 8; kc++) {
            qfr[kc][0] = __float_as_uint(Qr0[kc * 8 + tig    ]);
            qfr[kc][1] = __float_as_uint(Qr1[kc * 8 + tig    ]);
            qfr[kc][2] = __float_as_uint(Qr0[kc * 8 + tig + 4]);
            qfr[kc][3] = __float_as_uint(Qr1[kc * 8 + tig + 4]);
        }
    }

    const int lrow0 = tid >> 4;
    const int lc4   = (tid & 15) * 4;

    #define APREFETCH(TILE, STAGE)                                                  \
    {                                                                               \
        const int m0p = (TILE) * AKV;                                               \
        const uint32_t kBase = sBase + (uint32_t)((STAGE) * AKS_W) * 4;             \
        const uint32_t vBase = sBase + (uint32_t)(vsW + (STAGE) * AVS_W) * 4;       \
        _Pragma("unroll")                                                           \
        for (int it = 0; it < 2; it++) {                                            \
            int r = lrow0 + it * 16;                                                \
            cpasync16(kBase + (uint32_t)(r * KS2 + lc4) * 4,                        \
                      Kp + basek + (size_t)(m0p + r) * qstr + lc4);                 \
            cpasync16(vBase + (uint32_t)(r * VS2 + lc4) * 4,                        \
                      V + basev + (size_t)(m0p + r) * DIM + lc4);                   \
        }                                                                           \
        asm volatile("cp.async.commit_group;\n");                                   \
    }

    float acc_o[8][4];
    #pragma unroll
    for (int nb = 0; nb < 8; nb++)
        #pragma unroll
        for (int r = 0; r < 4; r++) acc_o[nb][r] = 0.0f;
    float rs0 = 0.0f, rs1 = 0.0f;

    const int NT = SEQ / AKV;
    APREFETCH(0, 0);
    APREFETCH(1, 1);

    for (int m = 0; m < NT; m++) {
        const int stage = m % NST;
        if (m + 1 < NT) {
            asm volatile("cp.async.wait_group 1;\n");
        } else {
            asm volatile("cp.async.wait_group 0;\n");
        }
        __syncthreads();
        if (m + 2 < NT) APREFETCH(m + 2, (m + 2) % NST);

        const uint32_t ksAddr = sBase + (uint32_t)(stage * AKS_W) * 4;
        const uint32_t vsOffW = vsW + stage * AVS_W;

        float acc_s[4][4] = {};
        #pragma unroll
        for (int k0 = 0; k0 < 64; k0 += 8) {
            uint32_t bK[2][4];
            #pragma unroll
            for (int nip = 0; nip < 2; nip++) {
                int row = (2 * nip + (lg >> 1)) * 8 + lr;
                int col = k0 + (lg & 1) * 4;
                ldsm_x4(bK[nip], ksAddr + (uint32_t)(row * KS2 + col) * 4);
            }
            #pragma unroll
            for (int ni = 0; ni < 4; ni++)
                mma_tf32(acc_s[ni], qfr[k0 >> 3], &bK[ni >> 1][(ni & 1) * 2]);
        }

        #pragma unroll
        for (int nb = 0; nb < 4; nb++) {
            float s00 = fmaf(0.5f, tanh_fast(acc_s[nb][0] * hs), 0.5f);
            float s01 = fmaf(0.5f, tanh_fast(acc_s[nb][1] * hs), 0.5f);
            float s10 = fmaf(0.5f, tanh_fast(acc_s[nb][2] * hs), 0.5f);
            float s11 = fmaf(0.5f, tanh_fast(acc_s[nb][3] * hs), 0.5f);
            rs0 += s00 + s01;
            rs1 += s10 + s11;
            aw[psW + (r0    ) * KS2 + nb * 8 + 2 * tig    ] = f2tf32(s00);
            aw[psW + (r0    ) * KS2 + nb * 8 + 2 * tig + 1] = f2tf32(s01);
            aw[psW + (r0 + 8) * KS2 + nb * 8 + 2 * tig    ] = f2tf32(s10);
            aw[psW + (r0 + 8) * KS2 + nb * 8 + 2 * tig + 1] = f2tf32(s11);
        }
        __syncwarp();

        #pragma unroll
        for (int k0 = 0; k0 < 32; k0 += 8) {
            uint32_t aP[4];
            {
                int row = warp * 16 + (lg & 1) * 8 + lr;
                int col = k0 + (lg >> 1) * 4;
                ldsm_x4(aP, psAddr + (uint32_t)(row * KS2 + col) * 4);
            }
            #pragma unroll
            for (int nb = 0; nb < 8; nb++) {
                uint32_t bfr[2];
                bfr[0] = aw[vsOffW + (k0 + tig    ) * VS2 + nb * 8 + gid];
                bfr[1] = aw[vsOffW + (k0 + tig + 4) * VS2 + nb * 8 + gid];
                mma_tf32(acc_o[nb], aP, bfr);
            }
        }
        __syncwarp();
    }
    #undef APREFETCH

    rs0 += __shfl_xor_sync(0xffffffffu, rs0, 1);
    rs0 += __shfl_xor_sync(0xffffffffu, rs0, 2);
    rs1 += __shfl_xor_sync(0xffffffffu, rs1, 1);
    rs1 += __shfl_xor_sync(0xffffffffu, rs1, 2);
    const float inv0 = 1.0f / fmaxf(rs0, 1.0f);
    const float inv1 = 1.0f / fmaxf(rs1, 1.0f);

    float* O0 = O + baseo + (size_t)r0 * DIM;
    float* O1 = O0 + 8 * DIM;
    #pragma unroll
    for (int nb = 0; nb < 8; nb++) {
        int col = nb * 8 + 2 * tig;
        uint2 a = make_uint2(f2tf32(acc_o[nb][0] * inv0), f2tf32(acc_o[nb][1] * inv0));
        uint2 c = make_uint2(f2tf32(acc_o[nb][2] * inv1), f2tf32(acc_o[nb][3] * inv1));
        *(uint2*)(O0 + col) = a;
        *(uint2*)(O1 + col) = c;
    }
}

// ---------------------------------------------------------------------------
// Host-side dispatch
// ---------------------------------------------------------------------------
struct Seg { const float* p; int s; };

template<int ACT, int EPI, bool HAS_BIAS, bool TF32OUT = false>
static void launch_gemm2(cudaStream_t st, const Seg* seg, int nseg,
                         const float* W0, const float* W1, int wsplit,
                         const float* bias,
                         const float* res1, const float* res2, const float* dtp,
                         float* C, int M, int N, int K)
{
    cudaFuncSetAttribute(gemm_tc_kernel<ACT, EPI, HAS_BIAS, TF32OUT>,
                         cudaFuncAttributeMaxDynamicSharedMemorySize, GEMM_SMEM);
    const float* p0 = seg[0].p;                     int s0 = seg[0].s;
    const float* p1 = (nseg > 1) ? seg[1].p : p0;   int s1 = (nseg > 1) ? seg[1].s : s0;
    const float* p2 = (nseg > 2) ? seg[2].p : p0;   int s2 = (nseg > 2) ? seg[2].s : s0;
    const float* p3 = (nseg > 3) ? seg[3].p : p0;   int s3 = (nseg > 3) ? seg[3].s : s0;
    dim3 g(N / BN, M / BM), b(256);
    gemm_tc_kernel<ACT, EPI, HAS_BIAS, TF32OUT><<<g, b, GEMM_SMEM, st>>>(
        p0, p1, p2, p3, s0, s1, s2, s3, W0, W1, wsplit,
        bias, res1, res2, dtp, C, M, N, K);
}

template<int ACT, int EPI, bool HAS_BIAS, bool TF32OUT = false>
static void launch_gemm(cudaStream_t st, const Seg* seg, int nseg,
                        const float* W, const float* bias,
                        const float* res1, const float* res2, const float* dtp,
                        float* C, int M, int N, int K)
{
    launch_gemm2<ACT, EPI, HAS_BIAS, TF32OUT>(st, seg, nseg, W, W, 1 << 30,
                                              bias, res1, res2, dtp, C, M, N, K);
}

static void roundcpy(cudaStream_t st, const float* src, float* dst, size_t n)
{
    int n4 = (int)(n / 4);
    roundcpy_kernel<<<(n4 + 255) / 256, 256, 0, st>>>(src, dst, n4);
}

static float* sym(const void* s)
{
    void* p = nullptr;
    cudaGetSymbolAddress(&p, s);
    return (float*)p;
}

extern "C" void kernel_launch(void* const* d_in, const int* in_sizes, int n_in,
                              void* d_out, int out_size)
{
    const float* z     = (const float*)d_in[0];
    const float* conn  = (const float*)d_in[1];
    const float* w_z   = (const float*)d_in[2];
    const float* w_c   = (const float*)d_in[3];
    const float* w_mlp = (const float*)d_in[4];
    const float* f_w1  = (const float*)d_in[5];
    const float* f_b1  = (const float*)d_in[6];
    const float* f_w2  = (const float*)d_in[7];
    const float* f_b2  = (const float*)d_in[8];
    const float* g_w1  = (const float*)d_in[9];
    const float* g_b1  = (const float*)d_in[10];
    const float* g_w2  = (const float*)d_in[11];
    const float* g_b2  = (const float*)d_in[12];
    const float* dt    = (const float*)d_in[13];
    const float* q_w   = (const float*)d_in[14];
    const float* k_w   = (const float*)d_in[15];
    const float* v_w   = (const float*)d_in[16];
    const float* o_w   = (const float*)d_in[17];
    const float* temp  = (const float*)d_in[18];
    const float* cu_w1 = (const float*)d_in[19];
    const float* cu_b1 = (const float*)d_in[20];
    const float* cu_w2 = (const float*)d_in[21];
    const float* cu_b2 = (const float*)d_in[22];
    const float* m_w1  = (const float*)d_in[23];
    const float* m_b1  = (const float*)d_in[24];
    const float* m_w2  = (const float*)d_in[25];
    const float* m_b2  = (const float*)d_in[26];

    float* out_z2 = (float*)d_out;
    float* out_cn = out_z2 + (size_t)NTOK * DIM;
    float* out_zb = out_cn + (size_t)NTOK * DIM;

    float* zn   = sym(g_zn);
    float* cn   = sym(g_cn);
    float* hf   = sym(g_hf);
    float* dzl  = sym(g_dzl);
    float* gh   = sym(g_gh);
    float* dz   = sym(g_dz);
    float* QKb  = sym(g_QK);
    float* Vb   = sym(g_V);
    float* attn = sym(g_attn);
    float* z1   = sym(g_z1);
    float* hcu  = sym(g_hcu);
    float* z1n  = sym(g_z1n);
    float* h4   = sym(g_h4);
    float* connr= sym(g_connr);
    float* wr   = sym(g_wr);

    float* r_fw1 = wr;
    float* r_fw2 = r_fw1 + 2 * MEG;
    float* r_gw1 = r_fw2 + 2 * MEG;
    float* r_gw2 = r_gw1 + 2 * MEG;
    float* r_qw  = r_gw2 + 1 * MEG;
    float* r_kw  = r_qw  + 2 * MEG;
    float* r_vw  = r_kw  + 2 * MEG;
    float* r_ow  = r_vw  + 1 * MEG;
    float* r_cw1 = r_ow  + 1 * MEG;
    float* r_cw2 = r_cw1 + 6 * MEG;
    float* r_mw1 = r_cw2 + 2 * MEG;
    float* r_mw2 = r_mw1 + 4 * MEG;

    const int ND = NTOK * DIM;

    static cudaStream_t s2 = nullptr;
    static cudaEvent_t evF1 = nullptr, evJ1 = nullptr, evF2 = nullptr, evJ2 = nullptr;
    if (!s2) {
        cudaStreamCreateWithFlags(&s2, cudaStreamNonBlocking);
        cudaEventCreateWithFlags(&evF1, cudaEventDisableTiming);
        cudaEventCreateWithFlags(&evJ1, cudaEventDisableTiming);
        cudaEventCreateWithFlags(&evF2, cudaEventDisableTiming);
        cudaEventCreateWithFlags(&evJ2, cudaEventDisableTiming);
    }
    cudaStream_t s0 = 0;

    // 1. norms (fused pair) on main stream
    rms2_kernel<<<2 * NTOK, 256, 0, s0>>>(z, w_z, zn, conn, w_c, cn);

    // ---- fork 1 ----
    cudaEventRecord(evF1, s0);
    cudaStreamWaitEvent(s2, evF1, 0);

    // chain B (s2)
    cudaMemcpyAsync(out_zb, z, (size_t)ND * sizeof(float),
                    cudaMemcpyDeviceToDevice, s2);
    roundcpy(s2, q_w, r_qw, 2 * MEG);
    roundcpy(s2, k_w, r_kw, 2 * MEG);
    roundcpy(s2, v_w, r_vw, 1 * MEG);
    roundcpy(s2, conn, connr, (size_t)ND);
    { Seg s[2] = {{zn, DIM}, {cn, DIM}};
      launch_gemm2<0,0,false,true>(s2, s, 2, r_qw, r_kw, DIM, nullptr,
                                   nullptr, nullptr, nullptr,
                                   QKb, NTOK, 2*DIM, 2*DIM); }
    { Seg s[1] = {{zn, DIM}};
      launch_gemm<0,0,false,true>(s2, s, 1, r_vw, nullptr, nullptr, nullptr, nullptr,
                                  Vb, NTOK, DIM, DIM); }
    {
        cudaFuncSetAttribute(attn_tc_kernel,
                             cudaFuncAttributeMaxDynamicSharedMemorySize, ATTN_SMEM);
        dim3 g(SEQ / AQ, NHEAD, BATCH), b(256);
        attn_tc_kernel<<<g, b, ATTN_SMEM, s2>>>(QKb, QKb + DIM, 2 * DIM, Vb, temp, attn);
    }
    cudaEventRecord(evJ1, s2);

    // chain A (s0)
    roundcpy(s0, f_w1, r_fw1, 2 * MEG);
    roundcpy(s0, f_w2, r_fw2, 2 * MEG);
    roundcpy(s0, g_w1, r_gw1, 2 * MEG);
    roundcpy(s0, g_w2, r_gw2, 1 * MEG);
    roundcpy(s0, m_w1, r_mw1, 4 * MEG);
    roundcpy(s0, m_w2, r_mw2, 4 * MEG);
    { Seg s[1] = {{zn, DIM}};
      launch_gemm<1,0,true,true>(s0, s, 1, r_fw1, f_b1, nullptr, nullptr, nullptr,
                                 hf, NTOK, 2*DIM, DIM); }
    { Seg s[2] = {{hf, 2*DIM}, {hf + DIM, 2*DIM}};
      launch_gemm<0,0,true,true>(s0, s, 2, r_fw2, f_b2, nullptr, nullptr, nullptr,
                                 dzl, NTOK, DIM, 2*DIM); }
    { Seg s[2] = {{cn, DIM}, {dzl, DIM}};
      launch_gemm<2,0,true,true>(s0, s, 2, r_gw1, g_b1, nullptr, nullptr, nullptr,
                                 gh, NTOK, DIM, 2*DIM); }
    { Seg s[1] = {{gh, DIM}};
      launch_gemm<0,2,true,true>(s0, s, 1, r_gw2, g_b2, dzl, nullptr, dt,
                                 dz, NTOK, DIM, DIM); }
    roundcpy(s0, o_w, r_ow, 1 * MEG);
    roundcpy(s0, cu_w1, r_cw1, 6 * MEG);
    roundcpy(s0, cu_w2, r_cw2, 2 * MEG);

    // ---- join 1 ----
    cudaStreamWaitEvent(s0, evJ1, 0);

    // 6. z1 = z + dz + attn @ o_w^T
    { Seg s[1] = {{attn, DIM}};
      launch_gemm<0,3,false,true>(s0, s, 1, r_ow, nullptr, z, dz, nullptr,
                                  z1, NTOK, DIM, DIM); }

    // ---- fork 2 ----
    cudaEventRecord(evF2, s0);
    cudaStreamWaitEvent(s2, evF2, 0);

    // chain C (s2)
    { Seg s[3] = {{connr, DIM}, {z1, DIM}, {dz, DIM}};
      launch_gemm<1,0,true,true>(s2, s, 3, r_cw1, cu_b1, nullptr, nullptr, nullptr,
                                 hcu, NTOK, 2*DIM, 3*DIM); }
    { Seg s[2] = {{hcu, 2*DIM}, {hcu + DIM, 2*DIM}};
      launch_gemm<0,1,true,false>(s2, s, 2, r_cw2, cu_b2, conn, nullptr, nullptr,
                                  out_cn, NTOK, DIM, 2*DIM); }
    cudaEventRecord(evJ2, s2);

    // chain D (s0)
    rms_kernel<<<NTOK, 256, 0, s0>>>(z1, w_mlp, z1n);
    { Seg s[1] = {{z1n, DIM}};
      launch_gemm<1,0,true,true>(s0, s, 1, r_mw1, m_b1, nullptr, nullptr, nullptr,
                                 h4, NTOK, 4*DIM, DIM); }
    { Seg s[4] = {{h4, 4*DIM}, {h4 + DIM, 4*DIM}, {h4 + 2*DIM, 4*DIM}, {h4 + 3*DIM, 4*DIM}};
      launch_gemm<0,1,true,false>(s0, s, 4, r_mw2, m_b2, z1, nullptr, nullptr,
                                  out_z2, NTOK, DIM, 4*DIM); }

    // ---- join 2 ----
    cudaStreamWaitEvent(s0, evJ2, 0);
}

// round 15
// speedup vs baseline: 1.0969x; 1.0074x over previous
#include <cuda_runtime.h>
#include <math.h>
#include <stdint.h>

#define BATCH 2
#define SEQ   2048
#define DIM   1024
#define NHEAD 16
#define HDIM  64
#define NTOK  (BATCH*SEQ)   // 4096
#define MEG   (1024*1024)

// ---------------------------------------------------------------------------
// Scratch
// ---------------------------------------------------------------------------
__device__ float g_zn  [NTOK*DIM];     // tf32 bits
__device__ float g_cn  [NTOK*DIM];     // tf32 bits
__device__ float g_hf  [NTOK*2*DIM];   // tf32 bits
__device__ float g_dzl [NTOK*DIM];     // tf32 bits
__device__ float g_gh  [NTOK*DIM];     // tf32 bits
__device__ float g_dz  [NTOK*DIM];     // tf32 bits
__device__ float g_QK  [NTOK*2*DIM];   // tf32 bits; cols [0,1024)=Q, [1024,2048)=K
__device__ float g_V   [NTOK*DIM];     // tf32 bits
__device__ float g_attn[NTOK*DIM];     // tf32 bits
__device__ float g_z1  [NTOK*DIM];     // tf32 bits
__device__ float g_hcu [NTOK*2*DIM];   // tf32 bits
__device__ float g_z1n [NTOK*DIM];     // tf32 bits
__device__ float g_h4  [NTOK*4*DIM];   // tf32 bits
__device__ float g_connr[NTOK*DIM];    // rounded copy of conn
__device__ float g_wr  [29*MEG];       // rounded weights

// ---------------------------------------------------------------------------
// helpers
// ---------------------------------------------------------------------------
__device__ __forceinline__ uint32_t f2tf32(float f)
{
    uint32_t r;
    asm("cvt.rna.tf32.f32 %0, %1;" : "=r"(r) : "f"(f));
    return r;
}

__device__ __forceinline__ float tanh_fast(float x)
{
    float y;
    asm("tanh.approx.f32 %0, %1;" : "=f"(y) : "f"(x));
    return y;
}

__device__ __forceinline__ void mma_tf32(float* c, const uint32_t* a, const uint32_t* b)
{
    asm volatile("mma.sync.aligned.m16n8k8.row.col.f32.tf32.tf32.f32 "
                 "{%0,%1,%2,%3}, {%4,%5,%6,%7}, {%8,%9}, {%0,%1,%2,%3};"
                 : "+f"(c[0]), "+f"(c[1]), "+f"(c[2]), "+f"(c[3])
                 : "r"(a[0]), "r"(a[1]), "r"(a[2]), "r"(a[3]),
                   "r"(b[0]), "r"(b[1]));
}

// 4x (8x8 b16) ldmatrix == 4 tf32 fragments of an (8x4 b32) tile
__device__ __forceinline__ void ldsm_x4(uint32_t* r, uint32_t addr)
{
    asm volatile("ldmatrix.sync.aligned.m8n8.x4.shared.b16 {%0,%1,%2,%3}, [%4];"
                 : "=r"(r[0]), "=r"(r[1]), "=r"(r[2]), "=r"(r[3]) : "r"(addr));
}

__device__ __forceinline__ void cpasync16(uint32_t saddr, const void* g)
{
    asm volatile("cp.async.cg.shared.global [%0], [%1], 16;\n" :: "r"(saddr), "l"(g));
}

// ---------------------------------------------------------------------------
// roundcpy: dst = tf32_rna(src), vectorized
// ---------------------------------------------------------------------------
__global__ void roundcpy_kernel(const float* __restrict__ src, float* __restrict__ dst,
                                int n4)
{
    int i = blockIdx.x * blockDim.x + threadIdx.x;
    if (i < n4) {
        float4 v = ((const float4*)src)[i];
        uint4 t;
        t.x = f2tf32(v.x); t.y = f2tf32(v.y); t.z = f2tf32(v.z); t.w = f2tf32(v.w);
        ((uint4*)dst)[i] = t;
    }
}

// ---------------------------------------------------------------------------
// RMSNorm (outputs tf32-rounded — all consumers are GEMM A operands)
// ---------------------------------------------------------------------------
__global__ void rms2_kernel(const float* __restrict__ x0, const float* __restrict__ w0,
                            float* __restrict__ o0,
                            const float* __restrict__ x1, const float* __restrict__ w1,
                            float* __restrict__ o1)
{
    int rid = blockIdx.x;
    const float* x; const float* w; float* o; int row;
    if (rid < NTOK) { x = x0; w = w0; o = o0; row = rid; }
    else            { x = x1; w = w1; o = o1; row = rid - NTOK; }

    int t = threadIdx.x;
    const float4* xr = (const float4*)(x + (size_t)row * DIM);
    float4 v = xr[t];
    float ss = v.x*v.x + v.y*v.y + v.z*v.z + v.w*v.w;

    __shared__ float red[256];
    red[t] = ss;
    __syncthreads();
    for (int s = 128; s > 0; s >>= 1) {
        if (t < s) red[t] += red[t + s];
        __syncthreads();
    }
    float inv = rsqrtf(red[0] * (1.0f / DIM) + 1e-6f);
    float4 wv = ((const float4*)w)[t];
    uint4 ov;
    ov.x = f2tf32(v.x * inv * wv.x);
    ov.y = f2tf32(v.y * inv * wv.y);
    ov.z = f2tf32(v.z * inv * wv.z);
    ov.w = f2tf32(v.w * inv * wv.w);
    ((uint4*)(o + (size_t)row * DIM))[t] = ov;
}

__global__ void rms_kernel(const float* __restrict__ x, const float* __restrict__ w,
                           float* __restrict__ o)
{
    int row = blockIdx.x;
    int t   = threadIdx.x;
    const float4* xr = (const float4*)(x + (size_t)row * DIM);
    float4 v = xr[t];
    float ss = v.x*v.x + v.y*v.y + v.z*v.z + v.w*v.w;

    __shared__ float red[256];
    red[t] = ss;
    __syncthreads();
    for (int s = 128; s > 0; s >>= 1) {
        if (t < s) red[t] += red[t + s];
        __syncthreads();
    }
    float inv = rsqrtf(red[0] * (1.0f / DIM) + 1e-6f);
    float4 wv = ((const float4*)w)[t];
    uint4 ov;
    ov.x = f2tf32(v.x * inv * wv.x);
    ov.y = f2tf32(v.y * inv * wv.y);
    ov.z = f2tf32(v.z * inv * wv.z);
    ov.w = f2tf32(v.w * inv * wv.w);
    ((uint4*)(o + (size_t)row * DIM))[t] = ov;
}

// ---------------------------------------------------------------------------
// TF32 tensor-core GEMM, all inputs pre-rounded tf32 bits (R14 version):
// 3-stage cp.async, one __syncthreads per k-iter, pure ldsm+mma inner loop.
// EPI: 0 none | 1 +res1 | 2 dt*(res1+v) | 3 v+res1+res2
// ACT: 0 none | 1 silu | 2 tanh
// ---------------------------------------------------------------------------
#define BM 128
#define BN 128
#define BK 32
#define KST 36
#define SA (BM * KST)
#define GNST 3
#define GEMM_SMEM (GNST * 2 * SA * 4)   // 110592 bytes; 2 CTAs = 221 KB <= 228 KB

template<int ACT, int EPI, bool HAS_BIAS, bool TF32OUT>
__global__ __launch_bounds__(256)
void gemm_tc_kernel(const float* __restrict__ p0, const float* __restrict__ p1,
                    const float* __restrict__ p2, const float* __restrict__ p3,
                    int s0, int s1, int s2, int s3,
                    const float* __restrict__ W0, const float* __restrict__ W1,
                    int wsplit,
                    const float* __restrict__ bias,
                    const float* __restrict__ res1, const float* __restrict__ res2,
                    const float* __restrict__ dtp,
                    float* __restrict__ C, int M, int N, int K)
{
    extern __shared__ float dsm[];   // [A0 W0][A1 W1][A2 W2]
    const uint32_t smem0 = (uint32_t)__cvta_generic_to_shared(dsm);

    const int bm = blockIdx.y * BM;
    const int bn = blockIdx.x * BN;
    const int tid  = threadIdx.x;
    const int warp = tid >> 5;
    const int lane = tid & 31;
    const int gid  = lane >> 2;
    const int tig  = lane & 3;
    const int wm   = warp >> 1;
    const int wn   = warp & 1;
    const int lg   = lane >> 3;
    const int lr   = lane & 7;

    const int rbase = tid >> 3;
    const int c4    = (tid & 7) * 4;

    const float* Wb = (bn < wsplit) ? (W0 + (size_t)bn * K)
                                    : (W1 + (size_t)(bn - wsplit) * K);

    float acc[2][8][4];
    #pragma unroll
    for (int mi = 0; mi < 2; mi++)
        #pragma unroll
        for (int ni = 0; ni < 8; ni++)
            #pragma unroll
            for (int r = 0; r < 4; r++) acc[mi][ni][r] = 0.0f;

    const int KT = K / BK;

    #define PREFETCH(KT_IDX, STAGE)                                                 \
    {                                                                               \
        const int gk  = (KT_IDX) * BK;                                              \
        const int seg = gk >> 10;                                                   \
        const float* sp = (seg == 0) ? p0 : (seg == 1) ? p1 : (seg == 2) ? p2 : p3; \
        const int    st = (seg == 0) ? s0 : (seg == 1) ? s1 : (seg == 2) ? s2 : s3; \
        const int    ko = (gk & 1023) + c4;                                         \
        const uint32_t base = smem0 + (uint32_t)((STAGE) * 2 * SA) * 4;             \
        _Pragma("unroll")                                                           \
        for (int it = 0; it < 4; it++) {                                            \
            int r = rbase + it * 32;                                                \
            cpasync16(base + (uint32_t)(r * KST + c4) * 4,                          \
                      sp + (size_t)(bm + r) * st + ko);                             \
            cpasync16(base + (uint32_t)(SA + r * KST + c4) * 4,                     \
                      Wb + (size_t)r * K + gk + c4);                                \
        }                                                                           \
        asm volatile("cp.async.commit_group;\n");                                   \
    }

    PREFETCH(0, 0);
    PREFETCH(1, 1);

    for (int kt = 0; kt < KT; kt++) {
        const int stage = kt % GNST;
        if (kt + 1 < KT) {
            asm volatile("cp.async.wait_group 1;\n");
        } else {
            asm volatile("cp.async.wait_group 0;\n");
        }
        __syncthreads();
        if (kt + 2 < KT) PREFETCH(kt + 2, (kt + 2) % GNST);

        const uint32_t sAaddr = smem0 + (uint32_t)(stage * 2 * SA) * 4;
        const uint32_t sWaddr = sAaddr + (uint32_t)SA * 4;

        #pragma unroll
        for (int k0 = 0; k0 < BK; k0 += 8) {
            uint32_t afr[2][4], bq[4][4];
            #pragma unroll
            for (int mi = 0; mi < 2; mi++) {
                int row = wm * 32 + mi * 16 + (lg & 1) * 8 + lr;
                int col = k0 + (lg >> 1) * 4;
                ldsm_x4(afr[mi], sAaddr + (uint32_t)(row * KST + col) * 4);
            }
            #pragma unroll
            for (int nip = 0; nip < 4; nip++) {
                int row = wn * 64 + (2 * nip + (lg >> 1)) * 8 + lr;
                int col = k0 + (lg & 1) * 4;
                ldsm_x4(bq[nip], sWaddr + (uint32_t)(row * KST + col) * 4);
            }
            #pragma unroll
            for (int mi = 0; mi < 2; mi++)
                #pragma unroll
                for (int ni = 0; ni < 8; ni++)
                    mma_tf32(acc[mi][ni], afr[mi], &bq[ni >> 1][(ni & 1) * 2]);
        }
    }
    #undef PREFETCH

    const float dtv = (EPI == 2) ? dtp[0] : 0.0f;

    #pragma unroll
    for (int mi = 0; mi < 2; mi++) {
        int row = bm + wm * 32 + mi * 16 + gid;
        #pragma unroll
        for (int ni = 0; ni < 8; ni++) {
            int col = bn + wn * 64 + ni * 8 + 2 * tig;
            float b0 = 0.f, b1 = 0.f;
            if (HAS_BIAS) { b0 = bias[col]; b1 = bias[col + 1]; }
            #pragma unroll
            for (int half = 0; half < 2; half++) {
                int r = row + half * 8;
                float v0 = acc[mi][ni][half * 2 + 0] + b0;
                float v1 = acc[mi][ni][half * 2 + 1] + b1;
                if (ACT == 1) { v0 = v0 / (1.0f + __expf(-v0)); v1 = v1 / (1.0f + __expf(-v1)); }
                else if (ACT == 2) { v0 = tanhf(v0); v1 = tanhf(v1); }
                if (EPI == 1) {
                    const float2 rv = *(const float2*)(res1 + (size_t)r * N + col);
                    v0 += rv.x; v1 += rv.y;
                } else if (EPI == 2) {
                    const float2 rv = *(const float2*)(res1 + (size_t)r * N + col);
                    v0 = dtv * (rv.x + v0); v1 = dtv * (rv.y + v1);
                } else if (EPI == 3) {
                    const float2 ra2 = *(const float2*)(res1 + (size_t)r * N + col);
                    const float2 rb2 = *(const float2*)(res2 + (size_t)r * N + col);
                    v0 += ra2.x + rb2.x; v1 += ra2.y + rb2.y;
                }
                float o0 = v0, o1 = v1;
                if (TF32OUT) {
                    o0 = __uint_as_float(f2tf32(v0));
                    o1 = __uint_as_float(f2tf32(v1));
                }
                *(float2*)(C + (size_t)r * N + col) = make_float2(o0, o1);
            }
        }
    }
}

// ---------------------------------------------------------------------------
// Sigmoid attention (unchanged from R13/R14)
// ---------------------------------------------------------------------------
#define AQ  128
#define AKV 32
#define KS2 68
#define VS2 72
#define NST 3
#define AKS_W (AKV * KS2)
#define AVS_W (AKV * VS2)
#define APS_W (AQ * KS2)
#define ATTN_SMEM ((NST * (AKS_W + AVS_W) + APS_W) * 4)

__global__ __launch_bounds__(256)
void attn_tc_kernel(const float* __restrict__ Qp, const float* __restrict__ Kp,
                    int qstr,
                    const float* __restrict__ V, const float* __restrict__ temp,
                    float* __restrict__ O)
{
    extern __shared__ uint32_t aw[];
    const uint32_t sBase  = (uint32_t)__cvta_generic_to_shared(aw);
    const int vsW = NST * AKS_W;
    const int psW = NST * (AKS_W + AVS_W);
    const uint32_t psAddr = sBase + (uint32_t)psW * 4;

    const int b = blockIdx.z, h = blockIdx.y;
    const int q0 = blockIdx.x * AQ;
    const int tid = threadIdx.x;
    const int warp = tid >> 5, lane = tid & 31;
    const int gid = lane >> 2, tig = lane & 3;
    const int lg  = lane >> 3, lr  = lane & 7;

    const float hs = 0.0625f * temp[0];
    const size_t baseq  = ((size_t)(b * SEQ + q0)) * qstr + h * HDIM;
    const size_t basek  = ((size_t)(b * SEQ)) * qstr + h * HDIM;
    const size_t basev  = ((size_t)(b * SEQ)) * DIM + h * HDIM;
    const size_t baseo  = ((size_t)(b * SEQ + q0)) * DIM + h * HDIM;

    const int r0 = warp * 16 + gid;

    uint32_t qfr[8][4];
    {
        const float* Qr0 = Qp + baseq + (size_t)r0 * qstr;
        const float* Qr1 = Qr0 + (size_t)8 * qstr;
        #pragma unroll
        for (int kc = 0; kc < 8; kc++) {
            qfr[kc][0] = __float_as_uint(Qr0[kc * 8 + tig    ]);
            qfr[kc][1] = __float_as_uint(Qr1[kc * 8 + tig    ]);
            qfr[kc][2] = __float_as_uint(Qr0[kc * 8 + tig + 4]);
            qfr[kc][3] = __float_as_uint(Qr1[kc * 8 + tig + 4]);
        }
    }

    const int lrow0 = tid >> 4;
    const int lc4   = (tid & 15) * 4;

    #define APREFETCH(TILE, STAGE)                                                  \
    {                                                                               \
        const int m0p = (TILE) * AKV;                                               \
        const uint32_t kBase = sBase + (uint32_t)((STAGE) * AKS_W) * 4;             \
        const uint32_t vBase = sBase + (uint32_t)(vsW + (STAGE) * AVS_W) * 4;       \
        _Pragma("unroll")                                                           \
        for (int it = 0; it < 2; it++) {                                            \
            int r = lrow0 + it * 16;                                                \
            cpasync16(kBase + (uint32_t)(r * KS2 + lc4) * 4,                        \
                      Kp + basek + (size_t)(m0p + r) * qstr + lc4);                 \
            cpasync16(vBase + (uint32_t)(r * VS2 + lc4) * 4,                        \
                      V + basev + (size_t)(m0p + r) * DIM + lc4);                   \
        }                                                                           \
        asm volatile("cp.async.commit_group;\n");                                   \
    }

    float acc_o[8][4];
    #pragma unroll
    for (int nb = 0; nb < 8; nb++)
        #pragma unroll
        for (int r = 0; r < 4; r++) acc_o[nb][r] = 0.0f;
    float rs0 = 0.0f, rs1 = 0.0f;

    const int NT = SEQ / AKV;
    APREFETCH(0, 0);
    APREFETCH(1, 1);

    for (int m = 0; m < NT; m++) {
        const int stage = m % NST;
        if (m + 1 < NT) {
            asm volatile("cp.async.wait_group 1;\n");
        } else {
            asm volatile("cp.async.wait_group 0;\n");
        }
        __syncthreads();
        if (m + 2 < NT) APREFETCH(m + 2, (m + 2) % NST);

        const uint32_t ksAddr = sBase + (uint32_t)(stage * AKS_W) * 4;
        const uint32_t vsOffW = vsW + stage * AVS_W;

        float acc_s[4][4] = {};
        #pragma unroll
        for (int k0 = 0; k0 < 64; k0 += 8) {
            uint32_t bK[2][4];
            #pragma unroll
            for (int nip = 0; nip < 2; nip++) {
                int row = (2 * nip + (lg >> 1)) * 8 + lr;
                int col = k0 + (lg & 1) * 4;
                ldsm_x4(bK[nip], ksAddr + (uint32_t)(row * KS2 + col) * 4);
            }
            #pragma unroll
            for (int ni = 0; ni < 4; ni++)
                mma_tf32(acc_s[ni], qfr[k0 >> 3], &bK[ni >> 1][(ni & 1) * 2]);
        }

        #pragma unroll
        for (int nb = 0; nb < 4; nb++) {
            float s00 = fmaf(0.5f, tanh_fast(acc_s[nb][0] * hs), 0.5f);
            float s01 = fmaf(0.5f, tanh_fast(acc_s[nb][1] * hs), 0.5f);
            float s10 = fmaf(0.5f, tanh_fast(acc_s[nb][2] * hs), 0.5f);
            float s11 = fmaf(0.5f, tanh_fast(acc_s[nb][3] * hs), 0.5f);
            rs0 += s00 + s01;
            rs1 += s10 + s11;
            aw[psW + (r0    ) * KS2 + nb * 8 + 2 * tig    ] = f2tf32(s00);
            aw[psW + (r0    ) * KS2 + nb * 8 + 2 * tig + 1] = f2tf32(s01);
            aw[psW + (r0 + 8) * KS2 + nb * 8 + 2 * tig    ] = f2tf32(s10);
            aw[psW + (r0 + 8) * KS2 + nb * 8 + 2 * tig + 1] = f2tf32(s11);
        }
        __syncwarp();

        #pragma unroll
        for (int k0 = 0; k0 < 32; k0 += 8) {
            uint32_t aP[4];
            {
                int row = warp * 16 + (lg & 1) * 8 + lr;
                int col = k0 + (lg >> 1) * 4;
                ldsm_x4(aP, psAddr + (uint32_t)(row * KS2 + col) * 4);
            }
            #pragma unroll
            for (int nb = 0; nb < 8; nb++) {
                uint32_t bfr[2];
                bfr[0] = aw[vsOffW + (k0 + tig    ) * VS2 + nb * 8 + gid];
                bfr[1] = aw[vsOffW + (k0 + tig + 4) * VS2 + nb * 8 + gid];
                mma_tf32(acc_o[nb], aP, bfr);
            }
        }
        __syncwarp();
    }
    #undef APREFETCH

    rs0 += __shfl_xor_sync(0xffffffffu, rs0, 1);
    rs0 += __shfl_xor_sync(0xffffffffu, rs0, 2);
    rs1 += __shfl_xor_sync(0xffffffffu, rs1, 1);
    rs1 += __shfl_xor_sync(0xffffffffu, rs1, 2);
    const float inv0 = 1.0f / fmaxf(rs0, 1.0f);
    const float inv1 = 1.0f / fmaxf(rs1, 1.0f);

    float* O0 = O + baseo + (size_t)r0 * DIM;
    float* O1 = O0 + 8 * DIM;
    #pragma unroll
    for (int nb = 0; nb < 8; nb++) {
        int col = nb * 8 + 2 * tig;
        uint2 a = make_uint2(f2tf32(acc_o[nb][0] * inv0), f2tf32(acc_o[nb][1] * inv0));
        uint2 c = make_uint2(f2tf32(acc_o[nb][2] * inv1), f2tf32(acc_o[nb][3] * inv1));
        *(uint2*)(O0 + col) = a;
        *(uint2*)(O1 + col) = c;
    }
}

// ---------------------------------------------------------------------------
// Host-side dispatch
// ---------------------------------------------------------------------------
struct Seg { const float* p; int s; };

template<int ACT, int EPI, bool HAS_BIAS, bool TF32OUT = false>
static void launch_gemm2(cudaStream_t st, const Seg* seg, int nseg,
                         const float* W0, const float* W1, int wsplit,
                         const float* bias,
                         const float* res1, const float* res2, const float* dtp,
                         float* C, int M, int N, int K)
{
    cudaFuncSetAttribute(gemm_tc_kernel<ACT, EPI, HAS_BIAS, TF32OUT>,
                         cudaFuncAttributeMaxDynamicSharedMemorySize, GEMM_SMEM);
    const float* p0 = seg[0].p;                     int s0 = seg[0].s;
    const float* p1 = (nseg > 1) ? seg[1].p : p0;   int s1 = (nseg > 1) ? seg[1].s : s0;
    const float* p2 = (nseg > 2) ? seg[2].p : p0;   int s2 = (nseg > 2) ? seg[2].s : s0;
    const float* p3 = (nseg > 3) ? seg[3].p : p0;   int s3 = (nseg > 3) ? seg[3].s : s0;
    dim3 g(N / BN, M / BM), b(256);
    gemm_tc_kernel<ACT, EPI, HAS_BIAS, TF32OUT><<<g, b, GEMM_SMEM, st>>>(
        p0, p1, p2, p3, s0, s1, s2, s3, W0, W1, wsplit,
        bias, res1, res2, dtp, C, M, N, K);
}

template<int ACT, int EPI, bool HAS_BIAS, bool TF32OUT = false>
static void launch_gemm(cudaStream_t st, const Seg* seg, int nseg,
                        const float* W, const float* bias,
                        const float* res1, const float* res2, const float* dtp,
                        float* C, int M, int N, int K)
{
    launch_gemm2<ACT, EPI, HAS_BIAS, TF32OUT>(st, seg, nseg, W, W, 1 << 30,
                                              bias, res1, res2, dtp, C, M, N, K);
}

static void roundcpy(cudaStream_t st, const float* src, float* dst, size_t n)
{
    int n4 = (int)(n / 4);
    roundcpy_kernel<<<(n4 + 255) / 256, 256, 0, st>>>(src, dst, n4);
}

static float* sym(const void* s)
{
    void* p = nullptr;
    cudaGetSymbolAddress(&p, s);
    return (float*)p;
}

extern "C" void kernel_launch(void* const* d_in, const int* in_sizes, int n_in,
                              void* d_out, int out_size)
{
    const float* z     = (const float*)d_in[0];
    const float* conn  = (const float*)d_in[1];
    const float* w_z   = (const float*)d_in[2];
    const float* w_c   = (const float*)d_in[3];
    const float* w_mlp = (const float*)d_in[4];
    const float* f_w1  = (const float*)d_in[5];
    const float* f_b1  = (const float*)d_in[6];
    const float* f_w2  = (const float*)d_in[7];
    const float* f_b2  = (const float*)d_in[8];
    const float* g_w1  = (const float*)d_in[9];
    const float* g_b1  = (const float*)d_in[10];
    const float* g_w2  = (const float*)d_in[11];
    const float* g_b2  = (const float*)d_in[12];
    const float* dt    = (const float*)d_in[13];
    const float* q_w   = (const float*)d_in[14];
    const float* k_w   = (const float*)d_in[15];
    const float* v_w   = (const float*)d_in[16];
    const float* o_w   = (const float*)d_in[17];
    const float* temp  = (const float*)d_in[18];
    const float* cu_w1 = (const float*)d_in[19];
    const float* cu_b1 = (const float*)d_in[20];
    const float* cu_w2 = (const float*)d_in[21];
    const float* cu_b2 = (const float*)d_in[22];
    const float* m_w1  = (const float*)d_in[23];
    const float* m_b1  = (const float*)d_in[24];
    const float* m_w2  = (const float*)d_in[25];
    const float* m_b2  = (const float*)d_in[26];

    float* out_z2 = (float*)d_out;
    float* out_cn = out_z2 + (size_t)NTOK * DIM;
    float* out_zb = out_cn + (size_t)NTOK * DIM;

    float* zn   = sym(g_zn);
    float* cn   = sym(g_cn);
    float* hf   = sym(g_hf);
    float* dzl  = sym(g_dzl);
    float* gh   = sym(g_gh);
    float* dz   = sym(g_dz);
    float* QKb  = sym(g_QK);
    float* Vb   = sym(g_V);
    float* attn = sym(g_attn);
    float* z1   = sym(g_z1);
    float* hcu  = sym(g_hcu);
    float* z1n  = sym(g_z1n);
    float* h4   = sym(g_h4);
    float* connr= sym(g_connr);
    float* wr   = sym(g_wr);

    float* r_fw1 = wr;
    float* r_fw2 = r_fw1 + 2 * MEG;
    float* r_gw1 = r_fw2 + 2 * MEG;
    float* r_gw2 = r_gw1 + 2 * MEG;
    float* r_qw  = r_gw2 + 1 * MEG;
    float* r_kw  = r_qw  + 2 * MEG;
    float* r_vw  = r_kw  + 2 * MEG;
    float* r_ow  = r_vw  + 1 * MEG;
    float* r_cw1 = r_ow  + 1 * MEG;
    float* r_cw2 = r_cw1 + 6 * MEG;
    float* r_mw1 = r_cw2 + 2 * MEG;
    float* r_mw2 = r_mw1 + 4 * MEG;

    const int ND = NTOK * DIM;

    static cudaStream_t s2 = nullptr, s3 = nullptr;
    static cudaEvent_t evF1 = nullptr, evJ1 = nullptr, evF2 = nullptr, evJ2 = nullptr;
    static cudaEvent_t evStart = nullptr, evQKV = nullptr, evFG = nullptr,
                       evO = nullptr, evCU = nullptr, evM = nullptr;
    if (!s2) {
        cudaStreamCreateWithFlags(&s2, cudaStreamNonBlocking);
        cudaStreamCreateWithFlags(&s3, cudaStreamNonBlocking);
        cudaEventCreateWithFlags(&evF1, cudaEventDisableTiming);
        cudaEventCreateWithFlags(&evJ1, cudaEventDisableTiming);
        cudaEventCreateWithFlags(&evF2, cudaEventDisableTiming);
        cudaEventCreateWithFlags(&evJ2, cudaEventDisableTiming);
        cudaEventCreateWithFlags(&evStart, cudaEventDisableTiming);
        cudaEventCreateWithFlags(&evQKV, cudaEventDisableTiming);
        cudaEventCreateWithFlags(&evFG, cudaEventDisableTiming);
        cudaEventCreateWithFlags(&evO, cudaEventDisableTiming);
        cudaEventCreateWithFlags(&evCU, cudaEventDisableTiming);
        cudaEventCreateWithFlags(&evM, cudaEventDisableTiming);
    }
    cudaStream_t s0 = 0;

    // ---- fork s3 at entry: weight rounding depends on nothing ----
    cudaEventRecord(evStart, s0);
    cudaStreamWaitEvent(s3, evStart, 0);

    // s3: rounds in order of first use
    roundcpy(s3, q_w, r_qw, 2 * MEG);
    roundcpy(s3, k_w, r_kw, 2 * MEG);
    roundcpy(s3, v_w, r_vw, 1 * MEG);
    cudaEventRecord(evQKV, s3);
    roundcpy(s3, f_w1, r_fw1, 2 * MEG);
    roundcpy(s3, f_w2, r_fw2, 2 * MEG);
    roundcpy(s3, g_w1, r_gw1, 2 * MEG);
    roundcpy(s3, g_w2, r_gw2, 1 * MEG);
    cudaEventRecord(evFG, s3);
    roundcpy(s3, o_w, r_ow, 1 * MEG);
    cudaEventRecord(evO, s3);
    roundcpy(s3, cu_w1, r_cw1, 6 * MEG);
    roundcpy(s3, cu_w2, r_cw2, 2 * MEG);
    roundcpy(s3, conn, connr, (size_t)ND);
    cudaEventRecord(evCU, s3);
    roundcpy(s3, m_w1, r_mw1, 4 * MEG);
    roundcpy(s3, m_w2, r_mw2, 4 * MEG);
    cudaEventRecord(evM, s3);

    // 1. norms (fused pair) on main stream
    rms2_kernel<<<2 * NTOK, 256, 0, s0>>>(z, w_z, zn, conn, w_c, cn);

    // ---- fork 1 ----
    cudaEventRecord(evF1, s0);
    cudaStreamWaitEvent(s2, evF1, 0);

    // chain B (s2)
    cudaMemcpyAsync(out_zb, z, (size_t)ND * sizeof(float),
                    cudaMemcpyDeviceToDevice, s2);
    cudaStreamWaitEvent(s2, evQKV, 0);
    { Seg s[2] = {{zn, DIM}, {cn, DIM}};
      launch_gemm2<0,0,false,true>(s2, s, 2, r_qw, r_kw, DIM, nullptr,
                                   nullptr, nullptr, nullptr,
                                   QKb, NTOK, 2*DIM, 2*DIM); }
    { Seg s[1] = {{zn, DIM}};
      launch_gemm<0,0,false,true>(s2, s, 1, r_vw, nullptr, nullptr, nullptr, nullptr,
                                  Vb, NTOK, DIM, DIM); }
    {
        cudaFuncSetAttribute(attn_tc_kernel,
                             cudaFuncAttributeMaxDynamicSharedMemorySize, ATTN_SMEM);
        dim3 g(SEQ / AQ, NHEAD, BATCH), b(256);
        attn_tc_kernel<<<g, b, ATTN_SMEM, s2>>>(QKb, QKb + DIM, 2 * DIM, Vb, temp, attn);
    }
    cudaEventRecord(evJ1, s2);

    // chain A (s0)
    cudaStreamWaitEvent(s0, evFG, 0);
    { Seg s[1] = {{zn, DIM}};
      launch_gemm<1,0,true,true>(s0, s, 1, r_fw1, f_b1, nullptr, nullptr, nullptr,
                                 hf, NTOK, 2*DIM, DIM); }
    { Seg s[2] = {{hf, 2*DIM}, {hf + DIM, 2*DIM}};
      launch_gemm<0,0,true,true>(s0, s, 2, r_fw2, f_b2, nullptr, nullptr, nullptr,
                                 dzl, NTOK, DIM, 2*DIM); }
    { Seg s[2] = {{cn, DIM}, {dzl, DIM}};
      launch_gemm<2,0,true,true>(s0, s, 2, r_gw1, g_b1, nullptr, nullptr, nullptr,
                                 gh, NTOK, DIM, 2*DIM); }
    { Seg s[1] = {{gh, DIM}};
      launch_gemm<0,2,true,true>(s0, s, 1, r_gw2, g_b2, dzl, nullptr, dt,
                                 dz, NTOK, DIM, DIM); }

    // ---- join 1 ----
    cudaStreamWaitEvent(s0, evJ1, 0);
    cudaStreamWaitEvent(s0, evO, 0);

    // 6. z1 = z + dz + attn @ o_w^T
    { Seg s[1] = {{attn, DIM}};
      launch_gemm<0,3,false,true>(s0, s, 1, r_ow, nullptr, z, dz, nullptr,
                                  z1, NTOK, DIM, DIM); }

    // ---- fork 2 ----
    cudaEventRecord(evF2, s0);
    cudaStreamWaitEvent(s2, evF2, 0);

    // chain C (s2)
    cudaStreamWaitEvent(s2, evCU, 0);
    { Seg s[3] = {{connr, DIM}, {z1, DIM}, {dz, DIM}};
      launch_gemm<1,0,true,true>(s2, s, 3, r_cw1, cu_b1, nullptr, nullptr, nullptr,
                                 hcu, NTOK, 2*DIM, 3*DIM); }
    { Seg s[2] = {{hcu, 2*DIM}, {hcu + DIM, 2*DIM}};
      launch_gemm<0,1,true,false>(s2, s, 2, r_cw2, cu_b2, conn, nullptr, nullptr,
                                  out_cn, NTOK, DIM, 2*DIM); }
    cudaEventRecord(evJ2, s2);

    // chain D (s0)
    rms_kernel<<<NTOK, 256, 0, s0>>>(z1, w_mlp, z1n);
    cudaStreamWaitEvent(s0, evM, 0);
    { Seg s[1] = {{z1n, DIM}};
      launch_gemm<1,0,true,true>(s0, s, 1, r_mw1, m_b1, nullptr, nullptr, nullptr,
                                 h4, NTOK, 4*DIM, DIM); }
    { Seg s[4] = {{h4, 4*DIM}, {h4 + DIM, 4*DIM}, {h4 + 2*DIM, 4*DIM}, {h4 + 3*DIM, 4*DIM}};
      launch_gemm<0,1,true,false>(s0, s, 4, r_mw2, m_b2, z1, nullptr, nullptr,
                                  out_z2, NTOK, DIM, 4*DIM); }

    // ---- join 2 ----
    cudaStreamWaitEvent(s0, evJ2, 0);
}

// round 16
// speedup vs baseline: 1.1084x; 1.0104x over previous
#include <cuda_runtime.h>
#include <math.h>
#include <stdint.h>

#define BATCH 2
#define SEQ   2048
#define DIM   1024
#define NHEAD 16
#define HDIM  64
#define NTOK  (BATCH*SEQ)   // 4096
#define MEG   (1024*1024)

// ---------------------------------------------------------------------------
// Scratch
// ---------------------------------------------------------------------------
__device__ float g_zn  [NTOK*DIM];     // tf32 bits
__device__ float g_cn  [NTOK*DIM];     // tf32 bits
__device__ float g_hf  [NTOK*2*DIM];   // tf32 bits
__device__ float g_dzl [NTOK*DIM];     // tf32 bits
__device__ float g_gh  [NTOK*DIM];     // tf32 bits
__device__ float g_dz  [NTOK*DIM];     // tf32 bits
__device__ float g_QK  [NTOK*2*DIM];   // tf32 bits; cols [0,1024)=Q, [1024,2048)=K
__device__ float g_V   [NTOK*DIM];     // tf32 bits
__device__ float g_attn[NTOK*DIM];     // tf32 bits
__device__ float g_z1  [NTOK*DIM];     // tf32 bits
__device__ float g_hcu [NTOK*2*DIM];   // tf32 bits
__device__ float g_z1n [NTOK*DIM];     // tf32 bits
__device__ float g_h4  [NTOK*4*DIM];   // tf32 bits
__device__ float g_connr[NTOK*DIM];    // rounded copy of conn
__device__ float g_wr  [29*MEG];       // rounded weights

// ---------------------------------------------------------------------------
// helpers
// ---------------------------------------------------------------------------
__device__ __forceinline__ uint32_t f2tf32(float f)
{
    uint32_t r;
    asm("cvt.rna.tf32.f32 %0, %1;" : "=r"(r) : "f"(f));
    return r;
}

__device__ __forceinline__ float tanh_fast(float x)
{
    float y;
    asm("tanh.approx.f32 %0, %1;" : "=f"(y) : "f"(x));
    return y;
}

__device__ __forceinline__ void mma_tf32(float* c, const uint32_t* a, const uint32_t* b)
{
    asm volatile("mma.sync.aligned.m16n8k8.row.col.f32.tf32.tf32.f32 "
                 "{%0,%1,%2,%3}, {%4,%5,%6,%7}, {%8,%9}, {%0,%1,%2,%3};"
                 : "+f"(c[0]), "+f"(c[1]), "+f"(c[2]), "+f"(c[3])
                 : "r"(a[0]), "r"(a[1]), "r"(a[2]), "r"(a[3]),
                   "r"(b[0]), "r"(b[1]));
}

// 4x (8x8 b16) ldmatrix == 4 tf32 fragments of an (8x4 b32) tile
__device__ __forceinline__ void ldsm_x4(uint32_t* r, uint32_t addr)
{
    asm volatile("ldmatrix.sync.aligned.m8n8.x4.shared.b16 {%0,%1,%2,%3}, [%4];"
                 : "=r"(r[0]), "=r"(r[1]), "=r"(r[2]), "=r"(r[3]) : "r"(addr));
}

__device__ __forceinline__ void cpasync16(uint32_t saddr, const void* g)
{
    asm volatile("cp.async.cg.shared.global [%0], [%1], 16;\n" :: "r"(saddr), "l"(g));
}

// ---------------------------------------------------------------------------
// roundcpy: dst = tf32_rna(src), vectorized
// ---------------------------------------------------------------------------
__global__ void roundcpy_kernel(const float* __restrict__ src, float* __restrict__ dst,
                                int n4)
{
    int i = blockIdx.x * blockDim.x + threadIdx.x;
    if (i < n4) {
        float4 v = ((const float4*)src)[i];
        uint4 t;
        t.x = f2tf32(v.x); t.y = f2tf32(v.y); t.z = f2tf32(v.z); t.w = f2tf32(v.w);
        ((uint4*)dst)[i] = t;
    }
}

// ---------------------------------------------------------------------------
// RMSNorm (outputs tf32-rounded — all consumers are GEMM A operands)
// ---------------------------------------------------------------------------
__global__ void rms2_kernel(const float* __restrict__ x0, const float* __restrict__ w0,
                            float* __restrict__ o0,
                            const float* __restrict__ x1, const float* __restrict__ w1,
                            float* __restrict__ o1)
{
    int rid = blockIdx.x;
    const float* x; const float* w; float* o; int row;
    if (rid < NTOK) { x = x0; w = w0; o = o0; row = rid; }
    else            { x = x1; w = w1; o = o1; row = rid - NTOK; }

    int t = threadIdx.x;
    const float4* xr = (const float4*)(x + (size_t)row * DIM);
    float4 v = xr[t];
    float ss = v.x*v.x + v.y*v.y + v.z*v.z + v.w*v.w;

    __shared__ float red[256];
    red[t] = ss;
    __syncthreads();
    for (int s = 128; s > 0; s >>= 1) {
        if (t < s) red[t] += red[t + s];
        __syncthreads();
    }
    float inv = rsqrtf(red[0] * (1.0f / DIM) + 1e-6f);
    float4 wv = ((const float4*)w)[t];
    uint4 ov;
    ov.x = f2tf32(v.x * inv * wv.x);
    ov.y = f2tf32(v.y * inv * wv.y);
    ov.z = f2tf32(v.z * inv * wv.z);
    ov.w = f2tf32(v.w * inv * wv.w);
    ((uint4*)(o + (size_t)row * DIM))[t] = ov;
}

__global__ void rms_kernel(const float* __restrict__ x, const float* __restrict__ w,
                           float* __restrict__ o)
{
    int row = blockIdx.x;
    int t   = threadIdx.x;
    const float4* xr = (const float4*)(x + (size_t)row * DIM);
    float4 v = xr[t];
    float ss = v.x*v.x + v.y*v.y + v.z*v.z + v.w*v.w;

    __shared__ float red[256];
    red[t] = ss;
    __syncthreads();
    for (int s = 128; s > 0; s >>= 1) {
        if (t < s) red[t] += red[t + s];
        __syncthreads();
    }
    float inv = rsqrtf(red[0] * (1.0f / DIM) + 1e-6f);
    float4 wv = ((const float4*)w)[t];
    uint4 ov;
    ov.x = f2tf32(v.x * inv * wv.x);
    ov.y = f2tf32(v.y * inv * wv.y);
    ov.z = f2tf32(v.z * inv * wv.z);
    ov.w = f2tf32(v.w * inv * wv.w);
    ((uint4*)(o + (size_t)row * DIM))[t] = ov;
}

// ---------------------------------------------------------------------------
// TF32 tensor-core GEMM, all inputs pre-rounded tf32 bits:
// 3-stage cp.async, one __syncthreads per k-iter, pure ldsm+mma inner loop.
// EPI: 0 none | 1 +res1 | 2 dt*(res1+v) | 3 v+res1+res2
// ACT: 0 none | 1 silu | 2 tanh
// ---------------------------------------------------------------------------
#define BM 128
#define BN 128
#define BK 32
#define KST 36
#define SA (BM * KST)
#define GNST 3
#define GEMM_SMEM (GNST * 2 * SA * 4)   // 110592 bytes; 2 CTAs = 221 KB <= 228 KB

template<int ACT, int EPI, bool HAS_BIAS, bool TF32OUT>
__global__ __launch_bounds__(256)
void gemm_tc_kernel(const float* __restrict__ p0, const float* __restrict__ p1,
                    const float* __restrict__ p2, const float* __restrict__ p3,
                    int s0, int s1, int s2, int s3,
                    const float* __restrict__ W0, const float* __restrict__ W1,
                    int wsplit,
                    const float* __restrict__ bias,
                    const float* __restrict__ res1, const float* __restrict__ res2,
                    const float* __restrict__ dtp,
                    float* __restrict__ C, int M, int N, int K)
{
    extern __shared__ float dsm[];   // [A0 W0][A1 W1][A2 W2]
    const uint32_t smem0 = (uint32_t)__cvta_generic_to_shared(dsm);

    const int bm = blockIdx.y * BM;
    const int bn = blockIdx.x * BN;
    const int tid  = threadIdx.x;
    const int warp = tid >> 5;
    const int lane = tid & 31;
    const int gid  = lane >> 2;
    const int tig  = lane & 3;
    const int wm   = warp >> 1;
    const int wn   = warp & 1;
    const int lg   = lane >> 3;
    const int lr   = lane & 7;

    const int rbase = tid >> 3;
    const int c4    = (tid & 7) * 4;

    const float* Wb = (bn < wsplit) ? (W0 + (size_t)bn * K)
                                    : (W1 + (size_t)(bn - wsplit) * K);

    float acc[2][8][4];
    #pragma unroll
    for (int mi = 0; mi < 2; mi++)
        #pragma unroll
        for (int ni = 0; ni < 8; ni++)
            #pragma unroll
            for (int r = 0; r < 4; r++) acc[mi][ni][r] = 0.0f;

    const int KT = K / BK;

    #define PREFETCH(KT_IDX, STAGE)                                                 \
    {                                                                               \
        const int gk  = (KT_IDX) * BK;                                              \
        const int seg = gk >> 10;                                                   \
        const float* sp = (seg == 0) ? p0 : (seg == 1) ? p1 : (seg == 2) ? p2 : p3; \
        const int    st = (seg == 0) ? s0 : (seg == 1) ? s1 : (seg == 2) ? s2 : s3; \
        const int    ko = (gk & 1023) + c4;                                         \
        const uint32_t base = smem0 + (uint32_t)((STAGE) * 2 * SA) * 4;             \
        _Pragma("unroll")                                                           \
        for (int it = 0; it < 4; it++) {                                            \
            int r = rbase + it * 32;                                                \
            cpasync16(base + (uint32_t)(r * KST + c4) * 4,                          \
                      sp + (size_t)(bm + r) * st + ko);                             \
            cpasync16(base + (uint32_t)(SA + r * KST + c4) * 4,                     \
                      Wb + (size_t)r * K + gk + c4);                                \
        }                                                                           \
        asm volatile("cp.async.commit_group;\n");                                   \
    }

    PREFETCH(0, 0);
    PREFETCH(1, 1);

    for (int kt = 0; kt < KT; kt++) {
        const int stage = kt % GNST;
        if (kt + 1 < KT) {
            asm volatile("cp.async.wait_group 1;\n");
        } else {
            asm volatile("cp.async.wait_group 0;\n");
        }
        __syncthreads();
        if (kt + 2 < KT) PREFETCH(kt + 2, (kt + 2) % GNST);

        const uint32_t sAaddr = smem0 + (uint32_t)(stage * 2 * SA) * 4;
        const uint32_t sWaddr = sAaddr + (uint32_t)SA * 4;

        #pragma unroll
        for (int k0 = 0; k0 < BK; k0 += 8) {
            uint32_t afr[2][4], bq[4][4];
            #pragma unroll
            for (int mi = 0; mi < 2; mi++) {
                int row = wm * 32 + mi * 16 + (lg & 1) * 8 + lr;
                int col = k0 + (lg >> 1) * 4;
                ldsm_x4(afr[mi], sAaddr + (uint32_t)(row * KST + col) * 4);
            }
            #pragma unroll
            for (int nip = 0; nip < 4; nip++) {
                int row = wn * 64 + (2 * nip + (lg >> 1)) * 8 + lr;
                int col = k0 + (lg & 1) * 4;
                ldsm_x4(bq[nip], sWaddr + (uint32_t)(row * KST + col) * 4);
            }
            #pragma unroll
            for (int mi = 0; mi < 2; mi++)
                #pragma unroll
                for (int ni = 0; ni < 8; ni++)
                    mma_tf32(acc[mi][ni], afr[mi], &bq[ni >> 1][(ni & 1) * 2]);
        }
    }
    #undef PREFETCH

    const float dtv = (EPI == 2) ? dtp[0] : 0.0f;

    #pragma unroll
    for (int mi = 0; mi < 2; mi++) {
        int row = bm + wm * 32 + mi * 16 + gid;
        #pragma unroll
        for (int ni = 0; ni < 8; ni++) {
            int col = bn + wn * 64 + ni * 8 + 2 * tig;
            float b0 = 0.f, b1 = 0.f;
            if (HAS_BIAS) { b0 = bias[col]; b1 = bias[col + 1]; }
            #pragma unroll
            for (int half = 0; half < 2; half++) {
                int r = row + half * 8;
                float v0 = acc[mi][ni][half * 2 + 0] + b0;
                float v1 = acc[mi][ni][half * 2 + 1] + b1;
                if (ACT == 1) { v0 = v0 / (1.0f + __expf(-v0)); v1 = v1 / (1.0f + __expf(-v1)); }
                else if (ACT == 2) { v0 = tanhf(v0); v1 = tanhf(v1); }
                if (EPI == 1) {
                    const float2 rv = *(const float2*)(res1 + (size_t)r * N + col);
                    v0 += rv.x; v1 += rv.y;
                } else if (EPI == 2) {
                    const float2 rv = *(const float2*)(res1 + (size_t)r * N + col);
                    v0 = dtv * (rv.x + v0); v1 = dtv * (rv.y + v1);
                } else if (EPI == 3) {
                    const float2 ra2 = *(const float2*)(res1 + (size_t)r * N + col);
                    const float2 rb2 = *(const float2*)(res2 + (size_t)r * N + col);
                    v0 += ra2.x + rb2.x; v1 += ra2.y + rb2.y;
                }
                float o0 = v0, o1 = v1;
                if (TF32OUT) {
                    o0 = __uint_as_float(f2tf32(v0));
                    o1 = __uint_as_float(f2tf32(v1));
                }
                *(float2*)(C + (size_t)r * N + col) = make_float2(o0, o1);
            }
        }
    }
}

// ---------------------------------------------------------------------------
// Sigmoid attention (unchanged)
// ---------------------------------------------------------------------------
#define AQ  128
#define AKV 32
#define KS2 68
#define VS2 72
#define NST 3
#define AKS_W (AKV * KS2)
#define AVS_W (AKV * VS2)
#define APS_W (AQ * KS2)
#define ATTN_SMEM ((NST * (AKS_W + AVS_W) + APS_W) * 4)

__global__ __launch_bounds__(256)
void attn_tc_kernel(const float* __restrict__ Qp, const float* __restrict__ Kp,
                    int qstr,
                    const float* __restrict__ V, const float* __restrict__ temp,
                    float* __restrict__ O)
{
    extern __shared__ uint32_t aw[];
    const uint32_t sBase  = (uint32_t)__cvta_generic_to_shared(aw);
    const int vsW = NST * AKS_W;
    const int psW = NST * (AKS_W + AVS_W);
    const uint32_t psAddr = sBase + (uint32_t)psW * 4;

    const int b = blockIdx.z, h = blockIdx.y;
    const int q0 = blockIdx.x * AQ;
    const int tid = threadIdx.x;
    const int warp = tid >> 5, lane = tid & 31;
    const int gid = lane >> 2, tig = lane & 3;
    const int lg  = lane >> 3, lr  = lane & 7;

    const float hs = 0.0625f * temp[0];
    const size_t baseq  = ((size_t)(b * SEQ + q0)) * qstr + h * HDIM;
    const size_t basek  = ((size_t)(b * SEQ)) * qstr + h * HDIM;
    const size_t basev  = ((size_t)(b * SEQ)) * DIM + h * HDIM;
    const size_t baseo  = ((size_t)(b * SEQ + q0)) * DIM + h * HDIM;

    const int r0 = warp * 16 + gid;

    uint32_t qfr[8][4];
    {
        const float* Qr0 = Qp + baseq + (size_t)r0 * qstr;
        const float* Qr1 = Qr0 + (size_t)8 * qstr;
        #pragma unroll
        for (int kc = 0; kc < 8; kc++) {
            qfr[kc][0] = __float_as_uint(Qr0[kc * 8 + tig    ]);
            qfr[kc][1] = __float_as_uint(Qr1[kc * 8 + tig    ]);
            qfr[kc][2] = __float_as_uint(Qr0[kc * 8 + tig + 4]);
            qfr[kc][3] = __float_as_uint(Qr1[kc * 8 + tig + 4]);
        }
    }

    const int lrow0 = tid >> 4;
    const int lc4   = (tid & 15) * 4;

    #define APREFETCH(TILE, STAGE)                                                  \
    {                                                                               \
        const int m0p = (TILE) * AKV;                                               \
        const uint32_t kBase = sBase + (uint32_t)((STAGE) * AKS_W) * 4;             \
        const uint32_t vBase = sBase + (uint32_t)(vsW + (STAGE) * AVS_W) * 4;       \
        _Pragma("unroll")                                                           \
        for (int it = 0; it < 2; it++) {                                            \
            int r = lrow0 + it * 16;                                                \
            cpasync16(kBase + (uint32_t)(r * KS2 + lc4) * 4,                        \
                      Kp + basek + (size_t)(m0p + r) * qstr + lc4);                 \
            cpasync16(vBase + (uint32_t)(r * VS2 + lc4) * 4,                        \
                      V + basev + (size_t)(m0p + r) * DIM + lc4);                   \
        }                                                                           \
        asm volatile("cp.async.commit_group;\n");                                   \
    }

    float acc_o[8][4];
    #pragma unroll
    for (int nb = 0; nb < 8; nb++)
        #pragma unroll
        for (int r = 0; r < 4; r++) acc_o[nb][r] = 0.0f;
    float rs0 = 0.0f, rs1 = 0.0f;

    const int NT = SEQ / AKV;
    APREFETCH(0, 0);
    APREFETCH(1, 1);

    for (int m = 0; m < NT; m++) {
        const int stage = m % NST;
        if (m + 1 < NT) {
            asm volatile("cp.async.wait_group 1;\n");
        } else {
            asm volatile("cp.async.wait_group 0;\n");
        }
        __syncthreads();
        if (m + 2 < NT) APREFETCH(m + 2, (m + 2) % NST);

        const uint32_t ksAddr = sBase + (uint32_t)(stage * AKS_W) * 4;
        const uint32_t vsOffW = vsW + stage * AVS_W;

        float acc_s[4][4] = {};
        #pragma unroll
        for (int k0 = 0; k0 < 64; k0 += 8) {
            uint32_t bK[2][4];
            #pragma unroll
            for (int nip = 0; nip < 2; nip++) {
                int row = (2 * nip + (lg >> 1)) * 8 + lr;
                int col = k0 + (lg & 1) * 4;
                ldsm_x4(bK[nip], ksAddr + (uint32_t)(row * KS2 + col) * 4);
            }
            #pragma unroll
            for (int ni = 0; ni < 4; ni++)
                mma_tf32(acc_s[ni], qfr[k0 >> 3], &bK[ni >> 1][(ni & 1) * 2]);
        }

        #pragma unroll
        for (int nb = 0; nb < 4; nb++) {
            float s00 = fmaf(0.5f, tanh_fast(acc_s[nb][0] * hs), 0.5f);
            float s01 = fmaf(0.5f, tanh_fast(acc_s[nb][1] * hs), 0.5f);
            float s10 = fmaf(0.5f, tanh_fast(acc_s[nb][2] * hs), 0.5f);
            float s11 = fmaf(0.5f, tanh_fast(acc_s[nb][3] * hs), 0.5f);
            rs0 += s00 + s01;
            rs1 += s10 + s11;
            aw[psW + (r0    ) * KS2 + nb * 8 + 2 * tig    ] = f2tf32(s00);
            aw[psW + (r0    ) * KS2 + nb * 8 + 2 * tig + 1] = f2tf32(s01);
            aw[psW + (r0 + 8) * KS2 + nb * 8 + 2 * tig    ] = f2tf32(s10);
            aw[psW + (r0 + 8) * KS2 + nb * 8 + 2 * tig + 1] = f2tf32(s11);
        }
        __syncwarp();

        #pragma unroll
        for (int k0 = 0; k0 < 32; k0 += 8) {
            uint32_t aP[4];
            {
                int row = warp * 16 + (lg & 1) * 8 + lr;
                int col = k0 + (lg >> 1) * 4;
                ldsm_x4(aP, psAddr + (uint32_t)(row * KS2 + col) * 4);
            }
            #pragma unroll
            for (int nb = 0; nb < 8; nb++) {
                uint32_t bfr[2];
                bfr[0] = aw[vsOffW + (k0 + tig    ) * VS2 + nb * 8 + gid];
                bfr[1] = aw[vsOffW + (k0 + tig + 4) * VS2 + nb * 8 + gid];
                mma_tf32(acc_o[nb], aP, bfr);
            }
        }
        __syncwarp();
    }
    #undef APREFETCH

    rs0 += __shfl_xor_sync(0xffffffffu, rs0, 1);
    rs0 += __shfl_xor_sync(0xffffffffu, rs0, 2);
    rs1 += __shfl_xor_sync(0xffffffffu, rs1, 1);
    rs1 += __shfl_xor_sync(0xffffffffu, rs1, 2);
    const float inv0 = 1.0f / fmaxf(rs0, 1.0f);
    const float inv1 = 1.0f / fmaxf(rs1, 1.0f);

    float* O0 = O + baseo + (size_t)r0 * DIM;
    float* O1 = O0 + 8 * DIM;
    #pragma unroll
    for (int nb = 0; nb < 8; nb++) {
        int col = nb * 8 + 2 * tig;
        uint2 a = make_uint2(f2tf32(acc_o[nb][0] * inv0), f2tf32(acc_o[nb][1] * inv0));
        uint2 c = make_uint2(f2tf32(acc_o[nb][2] * inv1), f2tf32(acc_o[nb][3] * inv1));
        *(uint2*)(O0 + col) = a;
        *(uint2*)(O1 + col) = c;
    }
}

// ---------------------------------------------------------------------------
// Host-side dispatch
// ---------------------------------------------------------------------------
struct Seg { const float* p; int s; };

template<int ACT, int EPI, bool HAS_BIAS, bool TF32OUT = false>
static void launch_gemm2(cudaStream_t st, const Seg* seg, int nseg,
                         const float* W0, const float* W1, int wsplit,
                         const float* bias,
                         const float* res1, const float* res2, const float* dtp,
                         float* C, int M, int N, int K)
{
    cudaFuncSetAttribute(gemm_tc_kernel<ACT, EPI, HAS_BIAS, TF32OUT>,
                         cudaFuncAttributeMaxDynamicSharedMemorySize, GEMM_SMEM);
    const float* p0 = seg[0].p;                     int s0 = seg[0].s;
    const float* p1 = (nseg > 1) ? seg[1].p : p0;   int s1 = (nseg > 1) ? seg[1].s : s0;
    const float* p2 = (nseg > 2) ? seg[2].p : p0;   int s2 = (nseg > 2) ? seg[2].s : s0;
    const float* p3 = (nseg > 3) ? seg[3].p : p0;   int s3 = (nseg > 3) ? seg[3].s : s0;
    dim3 g(N / BN, M / BM), b(256);
    gemm_tc_kernel<ACT, EPI, HAS_BIAS, TF32OUT><<<g, b, GEMM_SMEM, st>>>(
        p0, p1, p2, p3, s0, s1, s2, s3, W0, W1, wsplit,
        bias, res1, res2, dtp, C, M, N, K);
}

template<int ACT, int EPI, bool HAS_BIAS, bool TF32OUT = false>
static void launch_gemm(cudaStream_t st, const Seg* seg, int nseg,
                        const float* W, const float* bias,
                        const float* res1, const float* res2, const float* dtp,
                        float* C, int M, int N, int K)
{
    launch_gemm2<ACT, EPI, HAS_BIAS, TF32OUT>(st, seg, nseg, W, W, 1 << 30,
                                              bias, res1, res2, dtp, C, M, N, K);
}

static void roundcpy(cudaStream_t st, const float* src, float* dst, size_t n)
{
    int n4 = (int)(n / 4);
    roundcpy_kernel<<<(n4 + 255) / 256, 256, 0, st>>>(src, dst, n4);
}

static float* sym(const void* s)
{
    void* p = nullptr;
    cudaGetSymbolAddress(&p, s);
    return (float*)p;
}

extern "C" void kernel_launch(void* const* d_in, const int* in_sizes, int n_in,
                              void* d_out, int out_size)
{
    const float* z     = (const float*)d_in[0];
    const float* conn  = (const float*)d_in[1];
    const float* w_z   = (const float*)d_in[2];
    const float* w_c   = (const float*)d_in[3];
    const float* w_mlp = (const float*)d_in[4];
    const float* f_w1  = (const float*)d_in[5];
    const float* f_b1  = (const float*)d_in[6];
    const float* f_w2  = (const float*)d_in[7];
    const float* f_b2  = (const float*)d_in[8];
    const float* g_w1  = (const float*)d_in[9];
    const float* g_b1  = (const float*)d_in[10];
    const float* g_w2  = (const float*)d_in[11];
    const float* g_b2  = (const float*)d_in[12];
    const float* dt    = (const float*)d_in[13];
    const float* q_w   = (const float*)d_in[14];
    const float* k_w   = (const float*)d_in[15];
    const float* v_w   = (const float*)d_in[16];
    const float* o_w   = (const float*)d_in[17];
    const float* temp  = (const float*)d_in[18];
    const float* cu_w1 = (const float*)d_in[19];
    const float* cu_b1 = (const float*)d_in[20];
    const float* cu_w2 = (const float*)d_in[21];
    const float* cu_b2 = (const float*)d_in[22];
    const float* m_w1  = (const float*)d_in[23];
    const float* m_b1  = (const float*)d_in[24];
    const float* m_w2  = (const float*)d_in[25];
    const float* m_b2  = (const float*)d_in[26];

    float* out_z2 = (float*)d_out;
    float* out_cn = out_z2 + (size_t)NTOK * DIM;
    float* out_zb = out_cn + (size_t)NTOK * DIM;

    float* zn   = sym(g_zn);
    float* cn   = sym(g_cn);
    float* hf   = sym(g_hf);
    float* dzl  = sym(g_dzl);
    float* gh   = sym(g_gh);
    float* dz   = sym(g_dz);
    float* QKb  = sym(g_QK);
    float* Vb   = sym(g_V);
    float* attn = sym(g_attn);
    float* z1   = sym(g_z1);
    float* hcu  = sym(g_hcu);
    float* z1n  = sym(g_z1n);
    float* h4   = sym(g_h4);
    float* connr= sym(g_connr);
    float* wr   = sym(g_wr);

    float* r_fw1 = wr;
    float* r_fw2 = r_fw1 + 2 * MEG;
    float* r_gw1 = r_fw2 + 2 * MEG;
    float* r_gw2 = r_gw1 + 2 * MEG;
    float* r_qw  = r_gw2 + 1 * MEG;
    float* r_kw  = r_qw  + 2 * MEG;
    float* r_vw  = r_kw  + 2 * MEG;
    float* r_ow  = r_vw  + 1 * MEG;
    float* r_cw1 = r_ow  + 1 * MEG;
    float* r_cw2 = r_cw1 + 6 * MEG;
    float* r_mw1 = r_cw2 + 2 * MEG;
    float* r_mw2 = r_mw1 + 4 * MEG;

    const int ND = NTOK * DIM;

    static cudaStream_t s2 = nullptr, s3 = nullptr;
    static cudaEvent_t evF1 = nullptr, evJ1 = nullptr, evF2 = nullptr, evJ2 = nullptr;
    static cudaEvent_t evStart = nullptr, evQKV = nullptr, evFG = nullptr,
                       evO = nullptr, evCU = nullptr, evM = nullptr,
                       evV = nullptr, evZB = nullptr;
    if (!s2) {
        cudaStreamCreateWithFlags(&s2, cudaStreamNonBlocking);
        cudaStreamCreateWithFlags(&s3, cudaStreamNonBlocking);
        cudaEventCreateWithFlags(&evF1, cudaEventDisableTiming);
        cudaEventCreateWithFlags(&evJ1, cudaEventDisableTiming);
        cudaEventCreateWithFlags(&evF2, cudaEventDisableTiming);
        cudaEventCreateWithFlags(&evJ2, cudaEventDisableTiming);
        cudaEventCreateWithFlags(&evStart, cudaEventDisableTiming);
        cudaEventCreateWithFlags(&evQKV, cudaEventDisableTiming);
        cudaEventCreateWithFlags(&evFG, cudaEventDisableTiming);
        cudaEventCreateWithFlags(&evO, cudaEventDisableTiming);
        cudaEventCreateWithFlags(&evCU, cudaEventDisableTiming);
        cudaEventCreateWithFlags(&evM, cudaEventDisableTiming);
        cudaEventCreateWithFlags(&evV, cudaEventDisableTiming);
        cudaEventCreateWithFlags(&evZB, cudaEventDisableTiming);
    }
    cudaStream_t s0 = 0;

    // ---- fork s3 at entry: weight rounding depends on nothing ----
    cudaEventRecord(evStart, s0);
    cudaStreamWaitEvent(s3, evStart, 0);

    // s3: rounds in order of first use, then V projection, then tail work
    roundcpy(s3, q_w, r_qw, 2 * MEG);
    roundcpy(s3, k_w, r_kw, 2 * MEG);
    roundcpy(s3, v_w, r_vw, 1 * MEG);
    cudaEventRecord(evQKV, s3);
    roundcpy(s3, f_w1, r_fw1, 2 * MEG);
    roundcpy(s3, f_w2, r_fw2, 2 * MEG);
    roundcpy(s3, g_w1, r_gw1, 2 * MEG);
    roundcpy(s3, g_w2, r_gw2, 1 * MEG);
    cudaEventRecord(evFG, s3);

    // 1. norms (fused pair) on main stream
    rms2_kernel<<<2 * NTOK, 256, 0, s0>>>(z, w_z, zn, conn, w_c, cn);

    // ---- fork 1 ----
    cudaEventRecord(evF1, s0);
    cudaStreamWaitEvent(s2, evF1, 0);
    cudaStreamWaitEvent(s3, evF1, 0);

    // s3: V projection runs concurrently with QK on s2
    { Seg s[1] = {{zn, DIM}};
      launch_gemm<0,0,false,true>(s3, s, 1, r_vw, nullptr, nullptr, nullptr, nullptr,
                                  Vb, NTOK, DIM, DIM); }
    cudaEventRecord(evV, s3);
    // s3 tail: remaining rounds + z_before copy (fully off critical path)
    roundcpy(s3, o_w, r_ow, 1 * MEG);
    cudaEventRecord(evO, s3);
    roundcpy(s3, cu_w1, r_cw1, 6 * MEG);
    roundcpy(s3, cu_w2, r_cw2, 2 * MEG);
    roundcpy(s3, conn, connr, (size_t)ND);
    cudaEventRecord(evCU, s3);
    roundcpy(s3, m_w1, r_mw1, 4 * MEG);
    roundcpy(s3, m_w2, r_mw2, 4 * MEG);
    cudaEventRecord(evM, s3);
    cudaMemcpyAsync(out_zb, z, (size_t)ND * sizeof(float),
                    cudaMemcpyDeviceToDevice, s3);
    cudaEventRecord(evZB, s3);

    // chain B (s2): QK projection then attention
    cudaStreamWaitEvent(s2, evQKV, 0);
    { Seg s[2] = {{zn, DIM}, {cn, DIM}};
      launch_gemm2<0,0,false,true>(s2, s, 2, r_qw, r_kw, DIM, nullptr,
                                   nullptr, nullptr, nullptr,
                                   QKb, NTOK, 2*DIM, 2*DIM); }
    cudaStreamWaitEvent(s2, evV, 0);
    {
        cudaFuncSetAttribute(attn_tc_kernel,
                             cudaFuncAttributeMaxDynamicSharedMemorySize, ATTN_SMEM);
        dim3 g(SEQ / AQ, NHEAD, BATCH), b(256);
        attn_tc_kernel<<<g, b, ATTN_SMEM, s2>>>(QKb, QKb + DIM, 2 * DIM, Vb, temp, attn);
    }
    cudaEventRecord(evJ1, s2);

    // chain A (s0)
    cudaStreamWaitEvent(s0, evFG, 0);
    { Seg s[1] = {{zn, DIM}};
      launch_gemm<1,0,true,true>(s0, s, 1, r_fw1, f_b1, nullptr, nullptr, nullptr,
                                 hf, NTOK, 2*DIM, DIM); }
    { Seg s[2] = {{hf, 2*DIM}, {hf + DIM, 2*DIM}};
      launch_gemm<0,0,true,true>(s0, s, 2, r_fw2, f_b2, nullptr, nullptr, nullptr,
                                 dzl, NTOK, DIM, 2*DIM); }
    { Seg s[2] = {{cn, DIM}, {dzl, DIM}};
      launch_gemm<2,0,true,true>(s0, s, 2, r_gw1, g_b1, nullptr, nullptr, nullptr,
                                 gh, NTOK, DIM, 2*DIM); }
    { Seg s[1] = {{gh, DIM}};
      launch_gemm<0,2,true,true>(s0, s, 1, r_gw2, g_b2, dzl, nullptr, dt,
                                 dz, NTOK, DIM, DIM); }

    // ---- join 1 ----
    cudaStreamWaitEvent(s0, evJ1, 0);
    cudaStreamWaitEvent(s0, evO, 0);

    // 6. z1 = z + dz + attn @ o_w^T
    { Seg s[1] = {{attn, DIM}};
      launch_gemm<0,3,false,true>(s0, s, 1, r_ow, nullptr, z, dz, nullptr,
                                  z1, NTOK, DIM, DIM); }

    // ---- fork 2 ----
    cudaEventRecord(evF2, s0);
    cudaStreamWaitEvent(s2, evF2, 0);

    // chain C (s2)
    cudaStreamWaitEvent(s2, evCU, 0);
    { Seg s[3] = {{connr, DIM}, {z1, DIM}, {dz, DIM}};
      launch_gemm<1,0,true,true>(s2, s, 3, r_cw1, cu_b1, nullptr, nullptr, nullptr,
                                 hcu, NTOK, 2*DIM, 3*DIM); }
    { Seg s[2] = {{hcu, 2*DIM}, {hcu + DIM, 2*DIM}};
      launch_gemm<0,1,true,false>(s2, s, 2, r_cw2, cu_b2, conn, nullptr, nullptr,
                                  out_cn, NTOK, DIM, 2*DIM); }
    cudaEventRecord(evJ2, s2);

    // chain D (s0)
    rms_kernel<<<NTOK, 256, 0, s0>>>(z1, w_mlp, z1n);
    cudaStreamWaitEvent(s0, evM, 0);
    { Seg s[1] = {{z1n, DIM}};
      launch_gemm<1,0,true,true>(s0, s, 1, r_mw1, m_b1, nullptr, nullptr, nullptr,
                                 h4, NTOK, 4*DIM, DIM); }
    { Seg s[4] = {{h4, 4*DIM}, {h4 + DIM, 4*DIM}, {h4 + 2*DIM, 4*DIM}, {h4 + 3*DIM, 4*DIM}};
      launch_gemm<0,1,true,false>(s0, s, 4, r_mw2, m_b2, z1, nullptr, nullptr,
                                  out_z2, NTOK, DIM, 4*DIM); }

    // ---- join 2: everything (incl. s3 tail) back on the captured stream ----
    cudaStreamWaitEvent(s0, evJ2, 0);
    cudaStreamWaitEvent(s0, evZB, 0);
}